// round 12
// baseline (speedup 1.0000x reference)
#include <cuda_runtime.h>
#include <cuda_bf16.h>
#include <math.h>
#include <stdint.h>

// ---------------- constants ----------------
#define Bb 4
#define Cc 48
#define Tt 512
#define Ff 65
#define L0 62
#define L1 509
#define N0 2048
#define N1 260
#define ROWS0 126976
#define ROWS1 132340
#define ROWSMAX 132340
#define CONV_ROWS 133120
#define XU_S  (ROWSMAX*192)
#define XW_S  ((size_t)ROWSMAX*768)
#define HS_S  ((size_t)ROWSMAX*384)
#define TSZ   (Bb*Cc*Tt*Ff)
#define EK2   544
#define EPSLN 1e-5f

#define SMEM_XL   ((2*128*36 + 2*32*136)*4)   // 71680
#define SMEM_N64  ((2*128*36 + 2*32*72)*4)    // 55296
#define SMEM_PERS ((2*128*36 + 192*72)*4)     // 92160

// ---------------- device scratch ----------------
__device__ float g_xu[2*XU_S];
__device__ float g_xw[4*XW_S];
__device__ float g_hseq[2*HS_S];
__device__ float g_h[2*4*2048*192];
__device__ float g_c[4*2048*192];
__device__ float g_wihp[8*192*768];
__device__ float g_whhp[8*192*768];
__device__ float g_bp[8*768];
__device__ float g_twt[4*1536*48];
__device__ float g_io[2*TSZ];
__device__ float g_eo[2*TSZ];
__device__ float g_q[(size_t)2*16*512*EK2];          // [bz][t][k]
__device__ float g_k[(size_t)2*16*EK2*512];          // [bz][k][t]
__device__ float g_v[2*16*512*780];
__device__ float g_attn[(size_t)2*16*512*512];
__device__ float g_av[2*16*512*780];
__device__ unsigned g_bcnt;
__device__ unsigned g_bgen;

__device__ __forceinline__ float sigf(float x){ return 1.f/(1.f+expf(-x)); }

__device__ __forceinline__ float tf32r(float x){
    uint32_t r; asm("cvt.rna.tf32.f32 %0, %1;" : "=r"(r) : "f"(x));
    return __uint_as_float(r);
}

__device__ __forceinline__ void mma_tf32(float* c, uint32_t a0, uint32_t a1,
                                         uint32_t a2, uint32_t a3,
                                         uint32_t b0, uint32_t b1){
    asm volatile("mma.sync.aligned.m16n8k8.row.col.f32.tf32.tf32.f32 "
        "{%0,%1,%2,%3}, {%4,%5,%6,%7}, {%8,%9}, {%0,%1,%2,%3};"
        : "+f"(c[0]), "+f"(c[1]), "+f"(c[2]), "+f"(c[3])
        : "r"(a0), "r"(a1), "r"(a2), "r"(a3), "r"(b0), "r"(b1));
}

// cp.async helpers
__device__ __forceinline__ void cp16(void* smem, const void* gmem){
    uint32_t s = (uint32_t)__cvta_generic_to_shared(smem);
    asm volatile("cp.async.ca.shared.global [%0], [%1], 16;\n" :: "r"(s), "l"(gmem) : "memory");
}
__device__ __forceinline__ void cp16cg(void* smem, const void* gmem){
    uint32_t s = (uint32_t)__cvta_generic_to_shared(smem);
    asm volatile("cp.async.cg.shared.global [%0], [%1], 16;\n" :: "r"(s), "l"(gmem) : "memory");
}
__device__ __forceinline__ void cp16z(void* smem, const void* gmem, bool valid){
    uint32_t s = (uint32_t)__cvta_generic_to_shared(smem);
    int sz = valid ? 16 : 0;
    asm volatile("cp.async.ca.shared.global [%0], [%1], 16, %2;\n" :: "r"(s), "l"(gmem), "r"(sz) : "memory");
}
__device__ __forceinline__ void cp_commit(){ asm volatile("cp.async.commit_group;\n" ::: "memory"); }
__device__ __forceinline__ void cp_wait0(){ asm volatile("cp.async.wait_group 0;\n" ::: "memory"); }
__device__ __forceinline__ void cp_wait1(){ asm volatile("cp.async.wait_group 1;\n" ::: "memory"); }

// ------------- shared tile indexing -------------
#define ASI(buf,m,k)  sA[(buf)*4608 + (m)*36 + (k)]
#define BXL(buf,k,n)  sB[(buf)*4352 + (k)*136 + (n)]
#define BN64(buf,k,n) sB[(buf)*2304 + (k)*72 + (n)]

#define WARP_IDS \
    int lane = tid & 31, warp = tid >> 5; \
    int wm = warp >> 1, wn = warp & 1;    \
    int gp = lane >> 2, qn = lane & 3;

#define LOAD_A128(buf, Aptr, lda, rowClamp, kcc) { \
    _Pragma("unroll") for (int rep = 0; rep < 4; ++rep) { \
        int idx = tid + rep*256; \
        int row = idx >> 3, seg = idx & 7; \
        int gr = row0 + row; if (gr > (rowClamp)) gr = (rowClamp); \
        cp16(&ASI(buf,row,seg*4), &(Aptr)[(size_t)gr*(lda) + (kcc) + seg*4]); } }

// L2-only variant (cross-SM coherence inside one launch)
#define LOAD_A128CG(buf, Aptr, lda, rowClamp, kcc) { \
    _Pragma("unroll") for (int rep = 0; rep < 4; ++rep) { \
        int idx = tid + rep*256; \
        int row = idx >> 3, seg = idx & 7; \
        int gr = row0 + row; if (gr > (rowClamp)) gr = (rowClamp); \
        cp16cg(&ASI(buf,row,seg*4), &(Aptr)[(size_t)gr*(lda) + (kcc) + seg*4]); } }

#define LOAD_BXL(buf, Bptr, ldb, kcc) { \
    _Pragma("unroll") for (int rep = 0; rep < 4; ++rep) { \
        int idx = tid + rep*256; \
        int k = idx >> 5, seg = idx & 31; \
        cp16(&BXL(buf,k,seg*4), &(Bptr)[(size_t)((kcc) + k)*(ldb) + col0 + seg*4]); } }

#define LOAD_BXL_G(buf, Bptr, ldb, kcc, Ncols) { \
    _Pragma("unroll") for (int rep = 0; rep < 4; ++rep) { \
        int idx = tid + rep*256; \
        int k = idx >> 5, seg = idx & 31; \
        int cc = col0 + seg*4; \
        bool val = (cc < (Ncols)); \
        const float* src = val ? &(Bptr)[(size_t)((kcc) + k)*(ldb) + cc] : (const float*)(Bptr); \
        cp16z(&BXL(buf,k,seg*4), src, val); } }

#define LOAD_BN64(buf, Bptr, ldb, kcc) { \
    _Pragma("unroll") for (int rep = 0; rep < 2; ++rep) { \
        int idx = tid + rep*256; \
        int k = idx >> 4, seg = idx & 15; \
        cp16(&BN64(buf,k,seg*4), &(Bptr)[(size_t)((kcc) + k)*(ldb) + col0 + seg*4]); } }

#define MMA_XL(buf) \
    _Pragma("unroll") for (int k8 = 0; k8 < 4; ++k8) { \
        int kb = k8*8 + qn; \
        int am0 = wm*32 + gp; \
        uint32_t a00=ASI(buf,am0,kb),    a01=ASI(buf,am0+8,kb); \
        uint32_t a02=ASI(buf,am0,kb+4),  a03=ASI(buf,am0+8,kb+4); \
        uint32_t a10=ASI(buf,am0+16,kb),   a11=ASI(buf,am0+24,kb); \
        uint32_t a12=ASI(buf,am0+16,kb+4), a13=ASI(buf,am0+24,kb+4); \
        int bn = wn*64 + gp; \
        _Pragma("unroll") for (int nt = 0; nt < 8; ++nt) { \
            uint32_t b0 = BXL(buf,kb,bn+nt*8), b1 = BXL(buf,kb+4,bn+nt*8); \
            mma_tf32(acc[0][nt], a00,a01,a02,a03, b0,b1); \
            mma_tf32(acc[1][nt], a10,a11,a12,a13, b0,b1); } }

#define MMA_N64(buf) \
    _Pragma("unroll") for (int k8 = 0; k8 < 4; ++k8) { \
        int kb = k8*8 + qn; \
        int am0 = wm*32 + gp; \
        uint32_t a00=ASI(buf,am0,kb),    a01=ASI(buf,am0+8,kb); \
        uint32_t a02=ASI(buf,am0,kb+4),  a03=ASI(buf,am0+8,kb+4); \
        uint32_t a10=ASI(buf,am0+16,kb),   a11=ASI(buf,am0+24,kb); \
        uint32_t a12=ASI(buf,am0+16,kb+4), a13=ASI(buf,am0+24,kb+4); \
        int bn = wn*32 + gp; \
        _Pragma("unroll") for (int nt = 0; nt < 4; ++nt) { \
            uint32_t b0 = BN64(buf,kb,bn+nt*8), b1 = BN64(buf,kb+4,bn+nt*8); \
            mma_tf32(acc[0][nt], a00,a01,a02,a03, b0,b1); \
            mma_tf32(acc[1][nt], a10,a11,a12,a13, b0,b1); } }

// B from persistent slab (pitch 72), absolute k offset kcc
#define MMA_SLAB(buf, kcc) \
    _Pragma("unroll") for (int k8 = 0; k8 < 4; ++k8) { \
        int kb = k8*8 + qn; \
        int am0 = wm*32 + gp; \
        uint32_t a00=ASI(buf,am0,kb),    a01=ASI(buf,am0+8,kb); \
        uint32_t a02=ASI(buf,am0,kb+4),  a03=ASI(buf,am0+8,kb+4); \
        uint32_t a10=ASI(buf,am0+16,kb),   a11=ASI(buf,am0+24,kb); \
        uint32_t a12=ASI(buf,am0+16,kb+4), a13=ASI(buf,am0+24,kb+4); \
        int bn = wn*32 + gp; \
        const uint32_t* B0 = &sW[((kcc)+kb)*72]; \
        const uint32_t* B1 = &sW[((kcc)+kb+4)*72]; \
        _Pragma("unroll") for (int nt = 0; nt < 4; ++nt) { \
            uint32_t b0 = B0[bn+nt*8], b1 = B1[bn+nt*8]; \
            mma_tf32(acc[0][nt], a00,a01,a02,a03, b0,b1); \
            mma_tf32(acc[1][nt], a10,a11,a12,a13, b0,b1); } }

// ---------------- weight packing ----------------
__global__ void pack_weights(const float* __restrict__ LWih, const float* __restrict__ LWhh,
                             const float* __restrict__ Lb,   const float* __restrict__ TW)
{
    int stride = gridDim.x * blockDim.x;
    int t0 = blockIdx.x * blockDim.x + threadIdx.x;
    for (int idx = t0; idx < 8*192*768; idx += stride) {
        int w = idx / (192*768);
        int r = idx - w*(192*768);
        int j = r / 768, col = r - j*768;
        int u = col >> 2, gt = col & 3;
        int g = (w>>2)*2 + ((w>>1)&1);
        int d = w & 1;
        size_t src = ((size_t)(g*2+d)*768 + gt*192 + u);
        g_wihp[idx] = tf32r(LWih[src*192 + j]);
        g_whhp[idx] = tf32r(LWhh[src*192 + j]);
    }
    for (int idx = t0; idx < 8*768; idx += stride) {
        int w = idx / 768, col = idx - w*768;
        int u = col >> 2, gt = col & 3;
        int g = (w>>2)*2 + ((w>>1)&1);
        int d = w & 1;
        g_bp[idx] = Lb[(g*2+d)*768 + gt*192 + u];
    }
    for (int idx = t0; idx < 4*1536*48; idx += stride) {
        int g = idx / (1536*48);
        int r = idx - g*(1536*48);
        int kk = r / 48, o = r - kk*48;
        int k = kk / 384, i = kk - k*384;
        g_twt[idx] = tf32r(TW[(((size_t)g*384 + i)*48 + o)*4 + k]);
    }
}

__global__ void zero_state()
{
    int stride = gridDim.x * blockDim.x;
    int t0 = blockIdx.x * blockDim.x + threadIdx.x;
    for (int i = t0; i < 2*4*2048*192; i += stride) g_h[i] = 0.f;
    for (int i = t0; i < 4*2048*192;   i += stride) g_c[i] = 0.f;
}

__global__ void bar_init(){ g_bcnt = 0; g_bgen = 0; }

// ---------------- LN over C + unfold, intra ----------------
__global__ void ln_unfold_intra(const float* __restrict__ x0, const float* __restrict__ x1,
                                const float* __restrict__ ng, const float* __restrict__ nb)
{
    int t = blockIdx.x, b = blockIdx.y, s = blockIdx.z;
    const float* src = s ? x1 : x0;
    __shared__ float zs[48*65];
    __shared__ float mu[65], inv[65];
    int tid = threadIdx.x;
    for (int i = tid; i < 48*65; i += 256) {
        int c = i / 65, f = i - c*65;
        zs[i] = src[((size_t)(b*48 + c)*512 + t)*65 + f];
    }
    __syncthreads();
    if (tid < 65) {
        float s1 = 0.f, s2 = 0.f;
        #pragma unroll
        for (int c = 0; c < 48; ++c) { float v = zs[c*65 + tid]; s1 += v; s2 += v*v; }
        float m = s1 * (1.f/48.f);
        mu[tid] = m;
        inv[tid] = rsqrtf(s2*(1.f/48.f) - m*m + EPSLN);
    }
    __syncthreads();
    size_t n = (size_t)b*512 + t;
    float* outp = g_xu + (size_t)s*XU_S + n*(size_t)L0*192;
    for (int i = tid; i < 48*L0*4; i += 256) {
        int c = i / (L0*4);
        int r = i - c*(L0*4);
        int l = r >> 2, k = r & 3;
        int q = l + k;
        float v = (zs[c*65 + q] - mu[q]) * inv[q] * ng[s*48 + c] + nb[s*48 + c];
        outp[(size_t)l*192 + c*4 + k] = v;
    }
}

// ---------------- LN over C + unfold, inter ----------------
__global__ void ln_unfold_inter(const float* __restrict__ ng, const float* __restrict__ nb)
{
    int t = blockIdx.x, b = blockIdx.y, s = blockIdx.z;
    const float* src = g_io + (size_t)s*TSZ;
    __shared__ float zs[48*65];
    __shared__ float mu[65], inv[65];
    int tid = threadIdx.x;
    for (int i = tid; i < 48*65; i += 256) {
        int c = i / 65, f = i - c*65;
        zs[i] = src[((size_t)(b*48 + c)*512 + t)*65 + f];
    }
    __syncthreads();
    if (tid < 65) {
        float s1 = 0.f, s2 = 0.f;
        #pragma unroll
        for (int c = 0; c < 48; ++c) { float v = zs[c*65 + tid]; s1 += v; s2 += v*v; }
        float m = s1 * (1.f/48.f);
        mu[tid] = m;
        inv[tid] = rsqrtf(s2*(1.f/48.f) - m*m + EPSLN);
    }
    __syncthreads();
    int gi = 2 + s;
    for (int i = tid; i < 48*65; i += 256) {
        int c = i / 65, f = i - c*65;
        float v = (zs[i] - mu[f]) * inv[f] * ng[gi*48 + c] + nb[gi*48 + c];
        size_t n = (size_t)b*65 + f;
        float* outp = g_xu + (size_t)s*XU_S + n*(size_t)L1*192;
        #pragma unroll
        for (int k = 0; k < 4; ++k) {
            int l = t - k;
            if (l >= 0 && l < L1) outp[(size_t)l*192 + c*4 + k] = v;
        }
    }
}

// ---------------- xw = xu @ Wih^T + b   (XL 128x128 tf32 mma) ----------------
__global__ void __launch_bounds__(256, 2) xw_gemm(int phase, int M)
{
    extern __shared__ uint32_t smemu[];
    uint32_t* sA = smemu;
    uint32_t* sB = smemu + 2*4608;
    int combo = blockIdx.z;
    int s = combo >> 1;
    const float* A    = g_xu + (size_t)s*XU_S;
    const float* Bw   = g_wihp + (size_t)(phase*4 + combo)*192*768;
    const float* bias = g_bp + (size_t)(phase*4 + combo)*768;
    float* Co = g_xw + (size_t)combo*XW_S;
    int row0 = blockIdx.y*128, col0 = blockIdx.x*128;
    int tid = threadIdx.x;
    WARP_IDS
    float acc[2][8][4] = {};
    LOAD_A128(0, A, 192, M-1, 0)
    LOAD_BXL(0, Bw, 768, 0)
    cp_commit();
    #pragma unroll
    for (int c = 0; c < 6; ++c) {
        int cur = c & 1;
        if (c < 5) {
            LOAD_A128(cur^1, A, 192, M-1, (c+1)*32)
            LOAD_BXL(cur^1, Bw, 768, (c+1)*32)
            cp_commit();
            cp_wait1();
        } else cp_wait0();
        __syncthreads();
        MMA_XL(cur)
        __syncthreads();
    }
    #pragma unroll
    for (int mt = 0; mt < 2; ++mt) {
        int r = row0 + wm*32 + mt*16 + gp;
        #pragma unroll
        for (int nt = 0; nt < 8; ++nt) {
            int cb = col0 + wn*64 + nt*8 + 2*qn;
            float b0v = bias[cb], b1v = bias[cb+1];
            if (r < M)
                *(float2*)&Co[(size_t)r*768 + cb] = make_float2(acc[mt][nt][0]+b0v, acc[mt][nt][1]+b1v);
            if (r + 8 < M)
                *(float2*)&Co[(size_t)(r+8)*768 + cb] = make_float2(acc[mt][nt][2]+b0v, acc[mt][nt][3]+b1v);
        }
    }
}

// ---------------- fused LSTM step (launch-chain, phase 0) ----------------
__global__ void __launch_bounds__(256, 2) lstm_step(int t, int phase, int parity, int Nseq, int Lc)
{
    extern __shared__ uint32_t smemu[];
    uint32_t* sA = smemu;
    uint32_t* sB = smemu + 2*4608;
    int combo = blockIdx.z;
    int s = combo >> 1, d = combo & 1;
    int tt = d ? (Lc - 1 - t) : t;
    const float* Ah = g_h + ((size_t)parity*4 + combo)*2048*192;
    float* Ho       = g_h + ((size_t)(parity ^ 1)*4 + combo)*2048*192;
    float* Cst      = g_c + (size_t)combo*2048*192;
    const float* Bw = g_whhp + (size_t)(phase*4 + combo)*192*768;
    const float* XW = g_xw + (size_t)combo*XW_S;
    float* hs = g_hseq + (size_t)s*HS_S;
    int row0 = blockIdx.y*128, col0 = blockIdx.x*64;
    int tid = threadIdx.x;
    WARP_IDS
    int odd = qn & 1;
    float acc[2][4][4] = {};
    LOAD_A128(0, Ah, 192, Nseq-1, 0)
    LOAD_BN64(0, Bw, 768, 0)
    cp_commit();
    #pragma unroll
    for (int c = 0; c < 6; ++c) {
        int cur = c & 1;
        if (c < 5) {
            LOAD_A128(cur^1, Ah, 192, Nseq-1, (c+1)*32)
            LOAD_BN64(cur^1, Bw, 768, (c+1)*32)
            cp_commit();
            cp_wait1();
        } else cp_wait0();
        __syncthreads();
        MMA_N64(cur)
        __syncthreads();
    }
    #pragma unroll
    for (int mt = 0; mt < 2; ++mt) {
        int rlo = row0 + wm*32 + mt*16 + gp;
        int rhi = rlo + 8;
        int row = odd ? rhi : rlo;
        #pragma unroll
        for (int nt = 0; nt < 4; ++nt) {
            float sx0 = __shfl_xor_sync(0xffffffffu, acc[mt][nt][0], 1);
            float sx1 = __shfl_xor_sync(0xffffffffu, acc[mt][nt][1], 1);
            float sx2 = __shfl_xor_sync(0xffffffffu, acc[mt][nt][2], 1);
            float sx3 = __shfl_xor_sync(0xffffffffu, acc[mt][nt][3], 1);
            float gi, gf, gg, go;
            if (!odd) { gi = acc[mt][nt][0]; gf = acc[mt][nt][1]; gg = sx0; go = sx1; }
            else      { gi = sx2; gf = sx3; gg = acc[mt][nt][2]; go = acc[mt][nt][3]; }
            if (row < Nseq) {
                int ug = (col0 >> 2) + wn*8 + nt*2 + (qn >> 1);
                float4 xv = *(const float4*)&XW[((size_t)row*Lc + tt)*768 + ug*4];
                float I = gi + xv.x, F = gf + xv.y, G = gg + xv.z, O = go + xv.w;
                float cp = Cst[(size_t)row*192 + ug];
                float cn = sigf(F)*cp + sigf(I)*tanhf(G);
                float hn = sigf(O)*tanhf(cn);
                Cst[(size_t)row*192 + ug] = cn;
                Ho[(size_t)row*192 + ug]  = hn;
                hs[((size_t)row*Lc + tt)*384 + d*192 + ug] = hn;
            }
        }
    }
}

// ---------------- persistent LSTM for phase 1 (509 steps in one launch) ----------------
// grid (12 coltiles, 3 rowtiles, 4 combos) = 144 blocks, one per SM.
// Whh slab resident in smem; A staged via cp.async.cg (L2-coherent) double buffer.
__global__ void __launch_bounds__(256, 1) lstm_persist1(int nblocks)
{
    extern __shared__ uint32_t smemu[];
    uint32_t* sA = smemu;              // [2][128][36]
    uint32_t* sW = smemu + 2*4608;     // [192][72]
    const int Nseq = N1, Lc = L1;
    int combo = blockIdx.z;
    int s = combo >> 1, d = combo & 1;
    int row0 = blockIdx.y*128, col0 = blockIdx.x*64;
    int tid = threadIdx.x;
    WARP_IDS
    int odd = qn & 1;

    // load persistent Whh slab (cols [col0, col0+64))
    {
        const float* Bw = g_whhp + (size_t)(1*4 + combo)*192*768;
        for (int i = tid; i < 192*16; i += 256) {
            int k = i >> 4, seg = i & 15;
            float4 v = *(const float4*)&Bw[(size_t)k*768 + col0 + seg*4];
            sW[k*72 + seg*4    ] = __float_as_uint(v.x);
            sW[k*72 + seg*4 + 1] = __float_as_uint(v.y);
            sW[k*72 + seg*4 + 2] = __float_as_uint(v.z);
            sW[k*72 + seg*4 + 3] = __float_as_uint(v.w);
        }
    }

    float* Cst = g_c + (size_t)combo*2048*192;
    float* H0  = g_h + ((size_t)0*4 + combo)*2048*192;
    float* H1  = g_h + ((size_t)1*4 + combo)*2048*192;
    const float* XW = g_xw + (size_t)combo*XW_S;
    float* hs = g_hseq + (size_t)s*HS_S;

    unsigned gen = 1;
    for (int t = 0; t < Lc; ++t) {
        int parity = t & 1;
        const float* Ah = parity ? H1 : H0;
        float* Ho       = parity ? H0 : H1;
        int tt = d ? (Lc - 1 - t) : t;
        float acc[2][4][4] = {};
        LOAD_A128CG(0, Ah, 192, Nseq-1, 0)
        cp_commit();
        #pragma unroll
        for (int c = 0; c < 6; ++c) {
            int cur = c & 1;
            if (c < 5) {
                LOAD_A128CG(cur^1, Ah, 192, Nseq-1, (c+1)*32)
                cp_commit();
                cp_wait1();
            } else cp_wait0();
            __syncthreads();
            MMA_SLAB(cur, c*32)
            __syncthreads();
        }
        #pragma unroll
        for (int mt = 0; mt < 2; ++mt) {
            int rlo = row0 + wm*32 + mt*16 + gp;
            int rhi = rlo + 8;
            int row = odd ? rhi : rlo;
            #pragma unroll
            for (int nt = 0; nt < 4; ++nt) {
                float sx0 = __shfl_xor_sync(0xffffffffu, acc[mt][nt][0], 1);
                float sx1 = __shfl_xor_sync(0xffffffffu, acc[mt][nt][1], 1);
                float sx2 = __shfl_xor_sync(0xffffffffu, acc[mt][nt][2], 1);
                float sx3 = __shfl_xor_sync(0xffffffffu, acc[mt][nt][3], 1);
                float gi, gf, gg, go;
                if (!odd) { gi = acc[mt][nt][0]; gf = acc[mt][nt][1]; gg = sx0; go = sx1; }
                else      { gi = sx2; gf = sx3; gg = acc[mt][nt][2]; go = acc[mt][nt][3]; }
                if (row < Nseq) {
                    int ug = (col0 >> 2) + wn*8 + nt*2 + (qn >> 1);
                    float4 xv = *(const float4*)&XW[((size_t)row*Lc + tt)*768 + ug*4];
                    float I = gi + xv.x, F = gf + xv.y, G = gg + xv.z, O = go + xv.w;
                    float cp = Cst[(size_t)row*192 + ug];
                    float cn = sigf(F)*cp + sigf(I)*tanhf(G);
                    float hn = sigf(O)*tanhf(cn);
                    Cst[(size_t)row*192 + ug] = cn;
                    Ho[(size_t)row*192 + ug]  = hn;
                    hs[((size_t)row*Lc + tt)*384 + d*192 + ug] = hn;
                }
            }
        }
        // grid barrier
        __syncthreads();
        if (tid == 0) {
            __threadfence();
            unsigned a = atomicAdd(&g_bcnt, 1);
            if (a == (unsigned)(nblocks - 1)) {
                g_bcnt = 0;
                __threadfence();
                atomicExch(&g_bgen, gen);
            } else {
                while (*(volatile unsigned*)&g_bgen < gen) {}
                __threadfence();
            }
        }
        __syncthreads();
        gen++;
    }
}

// ---------------- convT1d gather-GEMM + bias + residual  (M128N64) ----------------
__global__ void __launch_bounds__(256, 2) convt_gemm(int phase, const float* __restrict__ Tb,
                                                     const float* __restrict__ x0, const float* __restrict__ x1)
{
    extern __shared__ uint32_t smemu[];
    uint32_t* sA = smemu;
    uint32_t* sB = smemu + 2*4608;
    int s = blockIdx.z;
    int Lc   = phase ? L1 : L0;
    int Qlen = phase ? 512 : 65;
    const float* hs = g_hseq + (size_t)s*HS_S;
    const float* Bw = g_twt + (size_t)(phase*2 + s)*1536*48;
    int row0 = blockIdx.y*128, col0 = 0;
    (void)col0;
    int tid = threadIdx.x;
    WARP_IDS
    float acc[2][4][4] = {};

    #define CONV_LOAD(buf, kcc) { \
        int ktap = (kcc) / 384; \
        int i0 = (kcc) - ktap*384; \
        _Pragma("unroll") for (int rep = 0; rep < 4; ++rep) { \
            int idx = tid + rep*256; \
            int rr = idx >> 3, seg = idx & 7; \
            int gr = row0 + rr; \
            int n = gr / Qlen, q = gr - n*Qlen; \
            int l = q - ktap; \
            bool val = (l >= 0 && l < Lc); \
            const float* src = val ? &hs[((size_t)n*Lc + l)*384 + i0 + seg*4] : hs; \
            cp16z(&ASI(buf,rr,seg*4), src, val); } \
        _Pragma("unroll") for (int rep = 0; rep < 2; ++rep) { \
            int idx = tid + rep*256; \
            int k = idx >> 4, seg = idx & 15; \
            bool val = (seg*4 < 48); \
            const float* src = val ? &Bw[(size_t)((kcc) + k)*48 + seg*4] : Bw; \
            cp16z(&BN64(buf,k,seg*4), src, val); } }

    CONV_LOAD(0, 0)
    cp_commit();
    for (int c = 0; c < 48; ++c) {
        int cur = c & 1;
        if (c < 47) {
            CONV_LOAD(cur^1, (c+1)*32)
            cp_commit();
            cp_wait1();
        } else cp_wait0();
        __syncthreads();
        MMA_N64(cur)
        __syncthreads();
    }
    #undef CONV_LOAD
    int g = phase*2 + s;
    #pragma unroll
    for (int mt = 0; mt < 2; ++mt) {
        int rbase = row0 + wm*32 + mt*16 + gp;
        #pragma unroll
        for (int nt = 0; nt < 4; ++nt) {
            int cb = wn*32 + nt*8 + 2*qn;
            #pragma unroll
            for (int half = 0; half < 2; ++half) {
                int row = rbase + half*8;
                int n = row / Qlen, q = row - n*Qlen;
                #pragma unroll
                for (int j = 0; j < 2; ++j) {
                    int c = cb + j;
                    if (c < 48) {
                        float v = acc[mt][nt][half*2 + j] + Tb[g*48 + c];
                        if (phase == 0) {
                            int b = n >> 9, tpos = n & 511;
                            size_t oi = ((size_t)(b*48 + c)*512 + tpos)*65 + q;
                            const float* res = s ? x1 : x0;
                            g_io[(size_t)s*TSZ + oi] = v + res[oi];
                        } else {
                            int b = n / 65, f = n - b*65;
                            size_t oi = ((size_t)(b*48 + c)*512 + q)*65 + f;
                            g_eo[(size_t)s*TSZ + oi] = v + g_io[(size_t)s*TSZ + oi];
                        }
                    }
                }
            }
        }
    }
}

// ---------------- q/k/v head projections + leaky + LN (K written transposed) ----------------
__global__ void __launch_bounds__(256) qkv_kernel(
    const float* __restrict__ AWqk, const float* __restrict__ Abqk, const float* __restrict__ Aaqk,
    const float* __restrict__ Agqk, const float* __restrict__ Abgqk,
    const float* __restrict__ AWv,  const float* __restrict__ Abv,  const float* __restrict__ Aav,
    const float* __restrict__ Agv,  const float* __restrict__ Abgv)
{
    int t = blockIdx.x, b = blockIdx.y, s = blockIdx.z, tid = threadIdx.x;
    int lane = tid & 31, warp = tid >> 5;
    __shared__ float zs[3120];
    __shared__ float buf[780];
    __shared__ float red[32];
    const float* z = g_eo + (size_t)s*TSZ;
    for (int i = tid; i < 3120; i += 256) {
        int c = i / 65, f = i - c*65;
        zs[i] = z[((size_t)(b*48 + c)*512 + t)*65 + f];
    }
    __syncthreads();
    for (int grp = 0; grp < 12; ++grp) {
        int tensor = grp >> 2, h = grp & 3;
        int nvals;
        const float *W, *bb, *gam, *bet;
        float alpha;
        if (tensor < 2) {
            nvals = 520;
            int hh = (s*2 + tensor)*4 + h;
            W = AWqk + (size_t)hh*8*48; bb = Abqk + hh*8; alpha = Aaqk[hh];
            gam = Agqk + (size_t)hh*8*65; bet = Abgqk + (size_t)hh*8*65;
        } else {
            nvals = 780;
            int hh = s*4 + h;
            W = AWv + (size_t)hh*12*48; bb = Abv + hh*12; alpha = Aav[hh];
            gam = Agv + (size_t)hh*12*65; bet = Abgv + (size_t)hh*12*65;
        }
        float ls = 0.f, lq = 0.f;
        for (int idx = tid; idx < nvals; idx += 256) {
            int e = idx / 65, f = idx - e*65;
            float a = bb[e];
            const float* wr = W + e*48;
            #pragma unroll
            for (int c = 0; c < 48; ++c) a += zs[c*65 + f]*wr[c];
            a = a >= 0.f ? a : alpha*a;
            buf[idx] = a; ls += a; lq += a*a;
        }
        #pragma unroll
        for (int o = 16; o; o >>= 1) {
            ls += __shfl_xor_sync(0xffffffffu, ls, o);
            lq += __shfl_xor_sync(0xffffffffu, lq, o);
        }
        if (lane == 0) { red[warp] = ls; red[8 + warp] = lq; }
        __syncthreads();
        if (tid == 0) {
            float a = 0.f, c = 0.f;
            #pragma unroll
            for (int i = 0; i < 8; ++i) { a += red[i]; c += red[8 + i]; }
            red[16] = a; red[17] = c;
        }
        __syncthreads();
        float mu = red[16] / nvals;
        float inv = rsqrtf(red[17] / nvals - mu*mu + EPSLN);
        int bz = s*16 + b*4 + h;
        if (tensor == 0) {
            float* outp = g_q + ((size_t)bz*512 + t)*EK2;
            for (int idx = tid; idx < nvals; idx += 256)
                outp[idx] = (buf[idx] - mu)*inv*gam[idx] + bet[idx];
            if (tid < EK2 - 520) outp[520 + tid] = 0.f;
        } else if (tensor == 1) {
            float* outp = g_k + (size_t)bz*EK2*512;
            for (int idx = tid; idx < nvals; idx += 256)
                outp[(size_t)idx*512 + t] = (buf[idx] - mu)*inv*gam[idx] + bet[idx];
            if (tid < EK2 - 520) outp[(size_t)(520 + tid)*512 + t] = 0.f;
        } else {
            float* outp = g_v + ((size_t)bz*512 + t)*780;
            for (int idx = tid; idx < nvals; idx += 256)
                outp[idx] = (buf[idx] - mu)*inv*gam[idx] + bet[idx];
        }
        __syncthreads();
    }
}

// ---------------- QK^T (scaled, XL) ----------------
__global__ void __launch_bounds__(256, 2) qk_gemm()
{
    extern __shared__ uint32_t smemu[];
    uint32_t* sA = smemu;
    uint32_t* sB = smemu + 2*4608;
    int bz = blockIdx.z;
    const float* Q  = g_q + (size_t)bz*512*EK2;
    const float* Kt = g_k + (size_t)bz*EK2*512;
    float* Co = g_attn + (size_t)bz*512*512;
    int row0 = blockIdx.y*128, col0 = blockIdx.x*128;
    int tid = threadIdx.x;
    WARP_IDS
    float acc[2][8][4] = {};
    LOAD_A128(0, Q, EK2, 511, 0)
    LOAD_BXL(0, Kt, 512, 0)
    cp_commit();
    for (int c = 0; c < 17; ++c) {
        int cur = c & 1;
        if (c < 16) {
            LOAD_A128(cur^1, Q, EK2, 511, (c+1)*32)
            LOAD_BXL(cur^1, Kt, 512, (c+1)*32)
            cp_commit();
            cp_wait1();
        } else cp_wait0();
        __syncthreads();
        MMA_XL(cur)
        __syncthreads();
    }
    float rs = rsqrtf(520.f);
    #pragma unroll
    for (int mt = 0; mt < 2; ++mt) {
        int r = row0 + wm*32 + mt*16 + gp;
        #pragma unroll
        for (int nt = 0; nt < 8; ++nt) {
            int cb = col0 + wn*64 + nt*8 + 2*qn;
            *(float2*)&Co[(size_t)r*512 + cb]     = make_float2(acc[mt][nt][0]*rs, acc[mt][nt][1]*rs);
            *(float2*)&Co[(size_t)(r+8)*512 + cb] = make_float2(acc[mt][nt][2]*rs, acc[mt][nt][3]*rs);
        }
    }
}

// ---------------- row softmax ----------------
__global__ void __launch_bounds__(256) softmax_rows()
{
    int row = blockIdx.x, bz = blockIdx.y, tid = threadIdx.x;
    float* p = g_attn + (size_t)bz*512*512 + (size_t)row*512;
    __shared__ float sm[512];
    __shared__ float red[256];
    sm[tid] = p[tid]; sm[tid + 256] = p[tid + 256];
    red[tid] = fmaxf(sm[tid], sm[tid + 256]);
    __syncthreads();
    for (int st = 128; st > 0; st >>= 1) {
        if (tid < st) red[tid] = fmaxf(red[tid], red[tid + st]);
        __syncthreads();
    }
    float mx = red[0];
    __syncthreads();
    float e0 = expf(sm[tid] - mx), e1 = expf(sm[tid + 256] - mx);
    red[tid] = e0 + e1;
    __syncthreads();
    for (int st = 128; st > 0; st >>= 1) {
        if (tid < st) red[tid] += red[tid + st];
        __syncthreads();
    }
    float invs = 1.f / red[0];
    p[tid] = e0*invs; p[tid + 256] = e1*invs;
}

// ---------------- P @ V (XL) ----------------
__global__ void __launch_bounds__(256, 2) pv_gemm()
{
    extern __shared__ uint32_t smemu[];
    uint32_t* sA = smemu;
    uint32_t* sB = smemu + 2*4608;
    int bz = blockIdx.z;
    const float* A  = g_attn + (size_t)bz*512*512;
    const float* Bv = g_v + (size_t)bz*512*780;
    float* Co = g_av + (size_t)bz*512*780;
    int row0 = blockIdx.y*128, col0 = blockIdx.x*128;
    int tid = threadIdx.x;
    WARP_IDS
    float acc[2][8][4] = {};
    LOAD_A128(0, A, 512, 511, 0)
    LOAD_BXL_G(0, Bv, 780, 0, 780)
    cp_commit();
    for (int c = 0; c < 16; ++c) {
        int cur = c & 1;
        if (c < 15) {
            LOAD_A128(cur^1, A, 512, 511, (c+1)*32)
            LOAD_BXL_G(cur^1, Bv, 780, (c+1)*32, 780)
            cp_commit();
            cp_wait1();
        } else cp_wait0();
        __syncthreads();
        MMA_XL(cur)
        __syncthreads();
    }
    #pragma unroll
    for (int mt = 0; mt < 2; ++mt) {
        int r = row0 + wm*32 + mt*16 + gp;
        #pragma unroll
        for (int nt = 0; nt < 8; ++nt) {
            int cb = col0 + wn*64 + nt*8 + 2*qn;
            #pragma unroll
            for (int j = 0; j < 2; ++j) {
                int col = cb + j;
                if (col < 780) {
                    Co[(size_t)r*780 + col]     = acc[mt][nt][j];
                    Co[(size_t)(r+8)*780 + col] = acc[mt][nt][2 + j];
                }
            }
        }
    }
}

// ---------------- output projection + leaky + LN + residual ----------------
__global__ void __launch_bounds__(256) outproj_kernel(
    const float* __restrict__ AWp, const float* __restrict__ Abp, const float* __restrict__ Aap,
    const float* __restrict__ Agp, const float* __restrict__ Abgp, float* __restrict__ dout)
{
    int t = blockIdx.x, b = blockIdx.y, s = blockIdx.z, tid = threadIdx.x;
    int lane = tid & 31, warp = tid >> 5;
    __shared__ float os[3120];
    __shared__ float buf[3120];
    __shared__ float red[32];
    for (int i = tid; i < 3120; i += 256) {
        int c = i / 65, f = i - c*65;
        int h = c / 12, dv = c - h*12;
        os[i] = g_av[((size_t)((s*16 + b*4 + h)*512) + t)*780 + dv*65 + f];
    }
    __syncthreads();
    float alpha = Aap[s];
    float ls = 0.f, lq = 0.f;
    for (int idx = tid; idx < 3120; idx += 256) {
        int o = idx / 65, f = idx - o*65;
        float a = Abp[s*48 + o];
        const float* wr = AWp + (size_t)(s*48 + o)*48;
        #pragma unroll
        for (int c = 0; c < 48; ++c) a += os[c*65 + f]*wr[c];
        a = a >= 0.f ? a : alpha*a;
        buf[idx] = a; ls += a; lq += a*a;
    }
    #pragma unroll
    for (int o = 16; o; o >>= 1) {
        ls += __shfl_xor_sync(0xffffffffu, ls, o);
        lq += __shfl_xor_sync(0xffffffffu, lq, o);
    }
    if (lane == 0) { red[warp] = ls; red[8 + warp] = lq; }
    __syncthreads();
    if (tid == 0) {
        float a = 0.f, c = 0.f;
        #pragma unroll
        for (int i = 0; i < 8; ++i) { a += red[i]; c += red[8 + i]; }
        red[16] = a; red[17] = c;
    }
    __syncthreads();
    float mu = red[16] / 3120.f;
    float inv = rsqrtf(red[17] / 3120.f - mu*mu + EPSLN);
    for (int idx = tid; idx < 3120; idx += 256) {
        int o = idx / 65, f = idx - o*65;
        float v = (buf[idx] - mu)*inv*Agp[(s*48 + o)*65 + f] + Abgp[(s*48 + o)*65 + f]
                + g_eo[(size_t)s*TSZ + ((size_t)(b*48 + o)*512 + t)*65 + f];
        dout[(((size_t)(s*4 + b)*48 + o)*512 + t)*65 + f] = v;
    }
}

// ---------------- host launch ----------------
extern "C" void kernel_launch(void* const* d_in, const int* in_sizes, int n_in,
                              void* d_out, int out_size)
{
    const float* x     = (const float*)d_in[0];
    const float* c2    = (const float*)d_in[1];
    const float* ng    = (const float*)d_in[2];
    const float* nb    = (const float*)d_in[3];
    const float* LWih  = (const float*)d_in[4];
    const float* LWhh  = (const float*)d_in[5];
    const float* Lb    = (const float*)d_in[6];
    const float* TW    = (const float*)d_in[7];
    const float* Tb    = (const float*)d_in[8];
    const float* AWqk  = (const float*)d_in[9];
    const float* Abqk  = (const float*)d_in[10];
    const float* Aaqk  = (const float*)d_in[11];
    const float* Agqk  = (const float*)d_in[12];
    const float* Abgqk = (const float*)d_in[13];
    const float* AWv   = (const float*)d_in[14];
    const float* Abv   = (const float*)d_in[15];
    const float* Aav   = (const float*)d_in[16];
    const float* Agv   = (const float*)d_in[17];
    const float* Abgv  = (const float*)d_in[18];
    const float* AWp   = (const float*)d_in[19];
    const float* Abp   = (const float*)d_in[20];
    const float* Aap   = (const float*)d_in[21];
    const float* Agp   = (const float*)d_in[22];
    const float* Abgp  = (const float*)d_in[23];
    float* out = (float*)d_out;

    cudaFuncSetAttribute(xw_gemm,      cudaFuncAttributeMaxDynamicSharedMemorySize, SMEM_XL);
    cudaFuncSetAttribute(qk_gemm,      cudaFuncAttributeMaxDynamicSharedMemorySize, SMEM_XL);
    cudaFuncSetAttribute(pv_gemm,      cudaFuncAttributeMaxDynamicSharedMemorySize, SMEM_XL);
    cudaFuncSetAttribute(lstm_step,    cudaFuncAttributeMaxDynamicSharedMemorySize, SMEM_N64);
    cudaFuncSetAttribute(convt_gemm,   cudaFuncAttributeMaxDynamicSharedMemorySize, SMEM_N64);
    cudaFuncSetAttribute(lstm_persist1,cudaFuncAttributeMaxDynamicSharedMemorySize, SMEM_PERS);

    pack_weights<<<512, 256>>>(LWih, LWhh, Lb, TW);

    // ---- phase 0: intra (launch-chain LSTM) ----
    zero_state<<<512, 256>>>();
    ln_unfold_intra<<<dim3(512, 4, 2), 256>>>(x, c2, ng, nb);
    xw_gemm<<<dim3(6, (ROWS0 + 127)/128, 4), 256, SMEM_XL>>>(0, ROWS0);
    for (int t = 0; t < L0; ++t)
        lstm_step<<<dim3(12, 16, 4), 256, SMEM_N64>>>(t, 0, t & 1, N0, L0);
    convt_gemm<<<dim3(1, CONV_ROWS/128, 2), 256, SMEM_N64>>>(0, Tb, x, c2);

    // ---- phase 1: inter (persistent LSTM) ----
    zero_state<<<512, 256>>>();
    ln_unfold_inter<<<dim3(512, 4, 2), 256>>>(ng, nb);
    xw_gemm<<<dim3(6, (ROWS1 + 127)/128, 4), 256, SMEM_XL>>>(1, ROWS1);
    bar_init<<<1, 1>>>();
    lstm_persist1<<<dim3(12, 3, 4), 256, SMEM_PERS>>>(12*3*4);
    convt_gemm<<<dim3(1, CONV_ROWS/128, 2), 256, SMEM_N64>>>(1, Tb, x, c2);

    // ---- attention ----
    qkv_kernel<<<dim3(512, 4, 2), 256>>>(AWqk, Abqk, Aaqk, Agqk, Abgqk,
                                         AWv, Abv, Aav, Agv, Abgv);
    qk_gemm<<<dim3(4, 4, 32), 256, SMEM_XL>>>();
    softmax_rows<<<dim3(512, 32), 256>>>();
    pv_gemm<<<dim3(7, 4, 32), 256, SMEM_XL>>>();
    outproj_kernel<<<dim3(512, 4, 2), 256>>>(AWp, Abp, Aap, Agp, Abgp, out);
}

// round 13
// speedup vs baseline: 1.1261x; 1.1261x over previous
#include <cuda_runtime.h>
#include <cuda_bf16.h>
#include <math.h>
#include <stdint.h>

// ---------------- constants ----------------
#define Bb 4
#define Cc 48
#define Tt 512
#define Ff 65
#define L0 62
#define L1 509
#define N0 2048
#define N1 260
#define ROWS0 126976
#define ROWS1 132340
#define ROWSMAX 132340
#define CONV_ROWS 133120
#define XU_S  (ROWSMAX*192)
#define XW_S  ((size_t)ROWSMAX*768)
#define HS_S  ((size_t)ROWSMAX*384)
#define TSZ   (Bb*Cc*Tt*Ff)
#define EK2   544
#define EPSLN 1e-5f

#define SMEM_XL   ((2*128*36 + 2*32*136)*4)   // 71680  (qk/pv)
#define SMEM_N64  ((2*128*36 + 2*32*72)*4)    // 55296  (lstm1/convt)
#define SMEM_XXL  ((2*128*36 + 2*32*264)*4)   // 104448 (xw)
#define SMEM_LBIG ((2*64*36  + 2*32*264)*4)   // 86016  (lstm0)

// ---------------- device scratch ----------------
__device__ float g_xu[2*XU_S];
__device__ float g_xw[4*XW_S];
__device__ float g_hseq[2*HS_S];
__device__ float g_h[2*4*2048*192];
__device__ float g_c[4*2048*192];
__device__ float g_wihp[8*192*768];
__device__ float g_whhp[8*192*768];
__device__ float g_bp[8*768];
__device__ float g_twt[4*1536*48];
__device__ float g_io[2*TSZ];
__device__ float g_eo[2*TSZ];
__device__ float g_q[(size_t)2*16*512*EK2];          // [bz][t][k]
__device__ float g_k[(size_t)2*16*EK2*512];          // [bz][k][t]
__device__ float g_v[2*16*512*780];
__device__ float g_attn[(size_t)2*16*512*512];
__device__ float g_av[2*16*512*780];

__device__ __forceinline__ float sigf(float x){ return 1.f/(1.f+expf(-x)); }

__device__ __forceinline__ float tf32r(float x){
    uint32_t r; asm("cvt.rna.tf32.f32 %0, %1;" : "=r"(r) : "f"(x));
    return __uint_as_float(r);
}

__device__ __forceinline__ void mma_tf32(float* c, uint32_t a0, uint32_t a1,
                                         uint32_t a2, uint32_t a3,
                                         uint32_t b0, uint32_t b1){
    asm volatile("mma.sync.aligned.m16n8k8.row.col.f32.tf32.tf32.f32 "
        "{%0,%1,%2,%3}, {%4,%5,%6,%7}, {%8,%9}, {%0,%1,%2,%3};"
        : "+f"(c[0]), "+f"(c[1]), "+f"(c[2]), "+f"(c[3])
        : "r"(a0), "r"(a1), "r"(a2), "r"(a3), "r"(b0), "r"(b1));
}

// cp.async helpers
__device__ __forceinline__ void cp16(void* smem, const void* gmem){
    uint32_t s = (uint32_t)__cvta_generic_to_shared(smem);
    asm volatile("cp.async.ca.shared.global [%0], [%1], 16;\n" :: "r"(s), "l"(gmem) : "memory");
}
__device__ __forceinline__ void cp16z(void* smem, const void* gmem, bool valid){
    uint32_t s = (uint32_t)__cvta_generic_to_shared(smem);
    int sz = valid ? 16 : 0;
    asm volatile("cp.async.ca.shared.global [%0], [%1], 16, %2;\n" :: "r"(s), "l"(gmem), "r"(sz) : "memory");
}
__device__ __forceinline__ void cp_commit(){ asm volatile("cp.async.commit_group;\n" ::: "memory"); }
__device__ __forceinline__ void cp_wait0(){ asm volatile("cp.async.wait_group 0;\n" ::: "memory"); }
__device__ __forceinline__ void cp_wait1(){ asm volatile("cp.async.wait_group 1;\n" ::: "memory"); }

// ------------- shared tile indexing -------------
#define ASI(buf,m,k)   sA[(buf)*4608 + (m)*36 + (k)]   // 128-row A
#define AS64(buf,m,k)  sA[(buf)*2304 + (m)*36 + (k)]   // 64-row A
#define BXL(buf,k,n)   sB[(buf)*4352 + (k)*136 + (n)]  // 128-col B
#define BN64(buf,k,n)  sB[(buf)*2304 + (k)*72  + (n)]  // 64-col B
#define BXX(buf,k,n)   sB[(buf)*8448 + (k)*264 + (n)]  // 256-col B

#define WARP_IDS \
    int lane = tid & 31, warp = tid >> 5; \
    int wm = warp >> 1, wn = warp & 1;    \
    int gp = lane >> 2, qn = lane & 3;

#define WARP_IDS_XXL \
    int lane = tid & 31, warp = tid >> 5; \
    int wm = warp >> 2, wn = warp & 3;    \
    int gp = lane >> 2, qn = lane & 3;

#define LOAD_A128(buf, Aptr, lda, rowClamp, kcc) { \
    _Pragma("unroll") for (int rep = 0; rep < 4; ++rep) { \
        int idx = tid + rep*256; \
        int row = idx >> 3, seg = idx & 7; \
        int gr = row0 + row; if (gr > (rowClamp)) gr = (rowClamp); \
        cp16(&ASI(buf,row,seg*4), &(Aptr)[(size_t)gr*(lda) + (kcc) + seg*4]); } }

#define LOAD_A64(buf, Aptr, lda, rowClamp, kcc) { \
    _Pragma("unroll") for (int rep = 0; rep < 2; ++rep) { \
        int idx = tid + rep*256; \
        int row = idx >> 3, seg = idx & 7; \
        int gr = row0 + row; if (gr > (rowClamp)) gr = (rowClamp); \
        cp16(&AS64(buf,row,seg*4), &(Aptr)[(size_t)gr*(lda) + (kcc) + seg*4]); } }

#define LOAD_BXL(buf, Bptr, ldb, kcc) { \
    _Pragma("unroll") for (int rep = 0; rep < 4; ++rep) { \
        int idx = tid + rep*256; \
        int k = idx >> 5, seg = idx & 31; \
        cp16(&BXL(buf,k,seg*4), &(Bptr)[(size_t)((kcc) + k)*(ldb) + col0 + seg*4]); } }

#define LOAD_BXL_G(buf, Bptr, ldb, kcc, Ncols) { \
    _Pragma("unroll") for (int rep = 0; rep < 4; ++rep) { \
        int idx = tid + rep*256; \
        int k = idx >> 5, seg = idx & 31; \
        int cc = col0 + seg*4; \
        bool val = (cc < (Ncols)); \
        const float* src = val ? &(Bptr)[(size_t)((kcc) + k)*(ldb) + cc] : (const float*)(Bptr); \
        cp16z(&BXL(buf,k,seg*4), src, val); } }

#define LOAD_BN64(buf, Bptr, ldb, kcc) { \
    _Pragma("unroll") for (int rep = 0; rep < 2; ++rep) { \
        int idx = tid + rep*256; \
        int k = idx >> 4, seg = idx & 15; \
        cp16(&BN64(buf,k,seg*4), &(Bptr)[(size_t)((kcc) + k)*(ldb) + col0 + seg*4]); } }

#define LOAD_BXX(buf, Bptr, ldb, kcc) { \
    _Pragma("unroll") for (int rep = 0; rep < 8; ++rep) { \
        int idx = tid + rep*256; \
        int k = idx >> 6, seg = idx & 63; \
        cp16(&BXX(buf,k,seg*4), &(Bptr)[(size_t)((kcc) + k)*(ldb) + col0 + seg*4]); } }

#define MMA_XL(buf) \
    _Pragma("unroll") for (int k8 = 0; k8 < 4; ++k8) { \
        int kb = k8*8 + qn; \
        int am0 = wm*32 + gp; \
        uint32_t a00=ASI(buf,am0,kb),    a01=ASI(buf,am0+8,kb); \
        uint32_t a02=ASI(buf,am0,kb+4),  a03=ASI(buf,am0+8,kb+4); \
        uint32_t a10=ASI(buf,am0+16,kb),   a11=ASI(buf,am0+24,kb); \
        uint32_t a12=ASI(buf,am0+16,kb+4), a13=ASI(buf,am0+24,kb+4); \
        int bn = wn*64 + gp; \
        _Pragma("unroll") for (int nt = 0; nt < 8; ++nt) { \
            uint32_t b0 = BXL(buf,kb,bn+nt*8), b1 = BXL(buf,kb+4,bn+nt*8); \
            mma_tf32(acc[0][nt], a00,a01,a02,a03, b0,b1); \
            mma_tf32(acc[1][nt], a10,a11,a12,a13, b0,b1); } }

#define MMA_N64(buf) \
    _Pragma("unroll") for (int k8 = 0; k8 < 4; ++k8) { \
        int kb = k8*8 + qn; \
        int am0 = wm*32 + gp; \
        uint32_t a00=ASI(buf,am0,kb),    a01=ASI(buf,am0+8,kb); \
        uint32_t a02=ASI(buf,am0,kb+4),  a03=ASI(buf,am0+8,kb+4); \
        uint32_t a10=ASI(buf,am0+16,kb),   a11=ASI(buf,am0+24,kb); \
        uint32_t a12=ASI(buf,am0+16,kb+4), a13=ASI(buf,am0+24,kb+4); \
        int bn = wn*32 + gp; \
        _Pragma("unroll") for (int nt = 0; nt < 4; ++nt) { \
            uint32_t b0 = BN64(buf,kb,bn+nt*8), b1 = BN64(buf,kb+4,bn+nt*8); \
            mma_tf32(acc[0][nt], a00,a01,a02,a03, b0,b1); \
            mma_tf32(acc[1][nt], a10,a11,a12,a13, b0,b1); } }

// xw: block 128x256, warp tile 64x64, acc[4][8][4]
#define MMA_XW(buf) \
    _Pragma("unroll") for (int k8 = 0; k8 < 4; ++k8) { \
        int kb = k8*8 + qn; \
        int am0 = wm*64 + gp; \
        uint32_t af[4][4]; \
        _Pragma("unroll") for (int mt = 0; mt < 4; ++mt) { \
            af[mt][0]=ASI(buf,am0+mt*16,kb);    af[mt][1]=ASI(buf,am0+mt*16+8,kb); \
            af[mt][2]=ASI(buf,am0+mt*16,kb+4);  af[mt][3]=ASI(buf,am0+mt*16+8,kb+4); } \
        int bn = wn*64 + gp; \
        _Pragma("unroll") for (int nt = 0; nt < 8; ++nt) { \
            uint32_t b0 = BXX(buf,kb,bn+nt*8), b1 = BXX(buf,kb+4,bn+nt*8); \
            _Pragma("unroll") for (int mt = 0; mt < 4; ++mt) \
                mma_tf32(acc[mt][nt], af[mt][0],af[mt][1],af[mt][2],af[mt][3], b0,b1); } }

// lstm0: block 64x256, warp tile 32x64, acc[2][8][4]
#define MMA_LBIG(buf) \
    _Pragma("unroll") for (int k8 = 0; k8 < 4; ++k8) { \
        int kb = k8*8 + qn; \
        int am0 = wm*32 + gp; \
        uint32_t a00=AS64(buf,am0,kb),    a01=AS64(buf,am0+8,kb); \
        uint32_t a02=AS64(buf,am0,kb+4),  a03=AS64(buf,am0+8,kb+4); \
        uint32_t a10=AS64(buf,am0+16,kb),   a11=AS64(buf,am0+24,kb); \
        uint32_t a12=AS64(buf,am0+16,kb+4), a13=AS64(buf,am0+24,kb+4); \
        int bn = wn*64 + gp; \
        _Pragma("unroll") for (int nt = 0; nt < 8; ++nt) { \
            uint32_t b0 = BXX(buf,kb,bn+nt*8), b1 = BXX(buf,kb+4,bn+nt*8); \
            mma_tf32(acc[0][nt], a00,a01,a02,a03, b0,b1); \
            mma_tf32(acc[1][nt], a10,a11,a12,a13, b0,b1); } }

// ---------------- weight packing ----------------
__global__ void pack_weights(const float* __restrict__ LWih, const float* __restrict__ LWhh,
                             const float* __restrict__ Lb,   const float* __restrict__ TW)
{
    int stride = gridDim.x * blockDim.x;
    int t0 = blockIdx.x * blockDim.x + threadIdx.x;
    for (int idx = t0; idx < 8*192*768; idx += stride) {
        int w = idx / (192*768);
        int r = idx - w*(192*768);
        int j = r / 768, col = r - j*768;
        int u = col >> 2, gt = col & 3;
        int g = (w>>2)*2 + ((w>>1)&1);
        int d = w & 1;
        size_t src = ((size_t)(g*2+d)*768 + gt*192 + u);
        g_wihp[idx] = tf32r(LWih[src*192 + j]);
        g_whhp[idx] = tf32r(LWhh[src*192 + j]);
    }
    for (int idx = t0; idx < 8*768; idx += stride) {
        int w = idx / 768, col = idx - w*768;
        int u = col >> 2, gt = col & 3;
        int g = (w>>2)*2 + ((w>>1)&1);
        int d = w & 1;
        g_bp[idx] = Lb[(g*2+d)*768 + gt*192 + u];
    }
    for (int idx = t0; idx < 4*1536*48; idx += stride) {
        int g = idx / (1536*48);
        int r = idx - g*(1536*48);
        int kk = r / 48, o = r - kk*48;
        int k = kk / 384, i = kk - k*384;
        g_twt[idx] = tf32r(TW[(((size_t)g*384 + i)*48 + o)*4 + k]);
    }
}

__global__ void zero_state()
{
    int stride = gridDim.x * blockDim.x;
    int t0 = blockIdx.x * blockDim.x + threadIdx.x;
    for (int i = t0; i < 2*4*2048*192; i += stride) g_h[i] = 0.f;
    for (int i = t0; i < 4*2048*192;   i += stride) g_c[i] = 0.f;
}

// ---------------- LN over C + unfold, intra ----------------
__global__ void ln_unfold_intra(const float* __restrict__ x0, const float* __restrict__ x1,
                                const float* __restrict__ ng, const float* __restrict__ nb)
{
    int t = blockIdx.x, b = blockIdx.y, s = blockIdx.z;
    const float* src = s ? x1 : x0;
    __shared__ float zs[48*65];
    __shared__ float mu[65], inv[65];
    int tid = threadIdx.x;
    for (int i = tid; i < 48*65; i += 256) {
        int c = i / 65, f = i - c*65;
        zs[i] = src[((size_t)(b*48 + c)*512 + t)*65 + f];
    }
    __syncthreads();
    if (tid < 65) {
        float s1 = 0.f, s2 = 0.f;
        #pragma unroll
        for (int c = 0; c < 48; ++c) { float v = zs[c*65 + tid]; s1 += v; s2 += v*v; }
        float m = s1 * (1.f/48.f);
        mu[tid] = m;
        inv[tid] = rsqrtf(s2*(1.f/48.f) - m*m + EPSLN);
    }
    __syncthreads();
    size_t n = (size_t)b*512 + t;
    float* outp = g_xu + (size_t)s*XU_S + n*(size_t)L0*192;
    for (int i = tid; i < 48*L0*4; i += 256) {
        int c = i / (L0*4);
        int r = i - c*(L0*4);
        int l = r >> 2, k = r & 3;
        int q = l + k;
        float v = (zs[c*65 + q] - mu[q]) * inv[q] * ng[s*48 + c] + nb[s*48 + c];
        outp[(size_t)l*192 + c*4 + k] = v;
    }
}

// ---------------- LN over C + unfold, inter ----------------
__global__ void ln_unfold_inter(const float* __restrict__ ng, const float* __restrict__ nb)
{
    int t = blockIdx.x, b = blockIdx.y, s = blockIdx.z;
    const float* src = g_io + (size_t)s*TSZ;
    __shared__ float zs[48*65];
    __shared__ float mu[65], inv[65];
    int tid = threadIdx.x;
    for (int i = tid; i < 48*65; i += 256) {
        int c = i / 65, f = i - c*65;
        zs[i] = src[((size_t)(b*48 + c)*512 + t)*65 + f];
    }
    __syncthreads();
    if (tid < 65) {
        float s1 = 0.f, s2 = 0.f;
        #pragma unroll
        for (int c = 0; c < 48; ++c) { float v = zs[c*65 + tid]; s1 += v; s2 += v*v; }
        float m = s1 * (1.f/48.f);
        mu[tid] = m;
        inv[tid] = rsqrtf(s2*(1.f/48.f) - m*m + EPSLN);
    }
    __syncthreads();
    int gi = 2 + s;
    for (int i = tid; i < 48*65; i += 256) {
        int c = i / 65, f = i - c*65;
        float v = (zs[i] - mu[f]) * inv[f] * ng[gi*48 + c] + nb[gi*48 + c];
        size_t n = (size_t)b*65 + f;
        float* outp = g_xu + (size_t)s*XU_S + n*(size_t)L1*192;
        #pragma unroll
        for (int k = 0; k < 4; ++k) {
            int l = t - k;
            if (l >= 0 && l < L1) outp[(size_t)l*192 + c*4 + k] = v;
        }
    }
}

// ---------------- xw = xu @ Wih^T + b   (XXL 128x256 tf32 mma) ----------------
__global__ void __launch_bounds__(256, 1) xw_gemm(int phase, int M)
{
    extern __shared__ uint32_t smemu[];
    uint32_t* sA = smemu;              // [2][128][36]
    uint32_t* sB = smemu + 2*4608;     // [2][32][264]
    int combo = blockIdx.z;
    int s = combo >> 1;
    const float* A    = g_xu + (size_t)s*XU_S;
    const float* Bw   = g_wihp + (size_t)(phase*4 + combo)*192*768;
    const float* bias = g_bp + (size_t)(phase*4 + combo)*768;
    float* Co = g_xw + (size_t)combo*XW_S;
    int row0 = blockIdx.y*128, col0 = blockIdx.x*256;
    int tid = threadIdx.x;
    WARP_IDS_XXL
    float acc[4][8][4] = {};
    LOAD_A128(0, A, 192, M-1, 0)
    LOAD_BXX(0, Bw, 768, 0)
    cp_commit();
    #pragma unroll
    for (int c = 0; c < 6; ++c) {
        int cur = c & 1;
        if (c < 5) {
            LOAD_A128(cur^1, A, 192, M-1, (c+1)*32)
            LOAD_BXX(cur^1, Bw, 768, (c+1)*32)
            cp_commit();
            cp_wait1();
        } else cp_wait0();
        __syncthreads();
        MMA_XW(cur)
        __syncthreads();
    }
    #pragma unroll
    for (int mt = 0; mt < 4; ++mt) {
        int r = row0 + wm*64 + mt*16 + gp;
        #pragma unroll
        for (int nt = 0; nt < 8; ++nt) {
            int cb = col0 + wn*64 + nt*8 + 2*qn;
            float b0v = bias[cb], b1v = bias[cb+1];
            if (r < M)
                *(float2*)&Co[(size_t)r*768 + cb] = make_float2(acc[mt][nt][0]+b0v, acc[mt][nt][1]+b1v);
            if (r + 8 < M)
                *(float2*)&Co[(size_t)(r+8)*768 + cb] = make_float2(acc[mt][nt][2]+b0v, acc[mt][nt][3]+b1v);
        }
    }
}

// ---------------- fused LSTM step, phase 0 (64x256 blocks) ----------------
__global__ void __launch_bounds__(256, 1) lstm_step_big(int t, int parity)
{
    extern __shared__ uint32_t smemu[];
    uint32_t* sA = smemu;              // [2][64][36]
    uint32_t* sB = smemu + 2*2304;     // [2][32][264]
    const int Nseq = N0, Lc = L0, phase = 0;
    int combo = blockIdx.z;
    int s = combo >> 1, d = combo & 1;
    int tt = d ? (Lc - 1 - t) : t;
    const float* Ah = g_h + ((size_t)parity*4 + combo)*2048*192;
    float* Ho       = g_h + ((size_t)(parity ^ 1)*4 + combo)*2048*192;
    float* Cst      = g_c + (size_t)combo*2048*192;
    const float* Bw = g_whhp + (size_t)(phase*4 + combo)*192*768;
    const float* XW = g_xw + (size_t)combo*XW_S;
    float* hs = g_hseq + (size_t)s*HS_S;
    int row0 = blockIdx.y*64, col0 = blockIdx.x*256;
    int tid = threadIdx.x;
    WARP_IDS_XXL
    int odd = qn & 1;
    float acc[2][8][4] = {};
    LOAD_A64(0, Ah, 192, Nseq-1, 0)
    LOAD_BXX(0, Bw, 768, 0)
    cp_commit();
    #pragma unroll
    for (int c = 0; c < 6; ++c) {
        int cur = c & 1;
        if (c < 5) {
            LOAD_A64(cur^1, Ah, 192, Nseq-1, (c+1)*32)
            LOAD_BXX(cur^1, Bw, 768, (c+1)*32)
            cp_commit();
            cp_wait1();
        } else cp_wait0();
        __syncthreads();
        MMA_LBIG(cur)
        __syncthreads();
    }
    #pragma unroll
    for (int mt = 0; mt < 2; ++mt) {
        int rlo = row0 + wm*32 + mt*16 + gp;
        int rhi = rlo + 8;
        int row = odd ? rhi : rlo;
        #pragma unroll
        for (int nt = 0; nt < 8; ++nt) {
            float sx0 = __shfl_xor_sync(0xffffffffu, acc[mt][nt][0], 1);
            float sx1 = __shfl_xor_sync(0xffffffffu, acc[mt][nt][1], 1);
            float sx2 = __shfl_xor_sync(0xffffffffu, acc[mt][nt][2], 1);
            float sx3 = __shfl_xor_sync(0xffffffffu, acc[mt][nt][3], 1);
            float gi, gf, gg, go;
            if (!odd) { gi = acc[mt][nt][0]; gf = acc[mt][nt][1]; gg = sx0; go = sx1; }
            else      { gi = sx2; gf = sx3; gg = acc[mt][nt][2]; go = acc[mt][nt][3]; }
            if (row < Nseq) {
                int ug = (col0 >> 2) + wn*16 + nt*2 + (qn >> 1);
                float4 xv = *(const float4*)&XW[((size_t)row*Lc + tt)*768 + ug*4];
                float I = gi + xv.x, F = gf + xv.y, G = gg + xv.z, O = go + xv.w;
                float cp = Cst[(size_t)row*192 + ug];
                float cn = sigf(F)*cp + sigf(I)*tanhf(G);
                float hn = sigf(O)*tanhf(cn);
                Cst[(size_t)row*192 + ug] = cn;
                Ho[(size_t)row*192 + ug]  = hn;
                hs[((size_t)row*Lc + tt)*384 + d*192 + ug] = hn;
            }
        }
    }
}

// ---------------- fused LSTM step, phase 1 (128x64 blocks, launch chain) ----------------
__global__ void __launch_bounds__(256, 2) lstm_step(int t, int phase, int parity, int Nseq, int Lc)
{
    extern __shared__ uint32_t smemu[];
    uint32_t* sA = smemu;
    uint32_t* sB = smemu + 2*4608;
    int combo = blockIdx.z;
    int s = combo >> 1, d = combo & 1;
    int tt = d ? (Lc - 1 - t) : t;
    const float* Ah = g_h + ((size_t)parity*4 + combo)*2048*192;
    float* Ho       = g_h + ((size_t)(parity ^ 1)*4 + combo)*2048*192;
    float* Cst      = g_c + (size_t)combo*2048*192;
    const float* Bw = g_whhp + (size_t)(phase*4 + combo)*192*768;
    const float* XW = g_xw + (size_t)combo*XW_S;
    float* hs = g_hseq + (size_t)s*HS_S;
    int row0 = blockIdx.y*128, col0 = blockIdx.x*64;
    int tid = threadIdx.x;
    WARP_IDS
    int odd = qn & 1;
    float acc[2][4][4] = {};
    LOAD_A128(0, Ah, 192, Nseq-1, 0)
    LOAD_BN64(0, Bw, 768, 0)
    cp_commit();
    #pragma unroll
    for (int c = 0; c < 6; ++c) {
        int cur = c & 1;
        if (c < 5) {
            LOAD_A128(cur^1, Ah, 192, Nseq-1, (c+1)*32)
            LOAD_BN64(cur^1, Bw, 768, (c+1)*32)
            cp_commit();
            cp_wait1();
        } else cp_wait0();
        __syncthreads();
        MMA_N64(cur)
        __syncthreads();
    }
    #pragma unroll
    for (int mt = 0; mt < 2; ++mt) {
        int rlo = row0 + wm*32 + mt*16 + gp;
        int rhi = rlo + 8;
        int row = odd ? rhi : rlo;
        #pragma unroll
        for (int nt = 0; nt < 4; ++nt) {
            float sx0 = __shfl_xor_sync(0xffffffffu, acc[mt][nt][0], 1);
            float sx1 = __shfl_xor_sync(0xffffffffu, acc[mt][nt][1], 1);
            float sx2 = __shfl_xor_sync(0xffffffffu, acc[mt][nt][2], 1);
            float sx3 = __shfl_xor_sync(0xffffffffu, acc[mt][nt][3], 1);
            float gi, gf, gg, go;
            if (!odd) { gi = acc[mt][nt][0]; gf = acc[mt][nt][1]; gg = sx0; go = sx1; }
            else      { gi = sx2; gf = sx3; gg = acc[mt][nt][2]; go = acc[mt][nt][3]; }
            if (row < Nseq) {
                int ug = (col0 >> 2) + wn*8 + nt*2 + (qn >> 1);
                float4 xv = *(const float4*)&XW[((size_t)row*Lc + tt)*768 + ug*4];
                float I = gi + xv.x, F = gf + xv.y, G = gg + xv.z, O = go + xv.w;
                float cp = Cst[(size_t)row*192 + ug];
                float cn = sigf(F)*cp + sigf(I)*tanhf(G);
                float hn = sigf(O)*tanhf(cn);
                Cst[(size_t)row*192 + ug] = cn;
                Ho[(size_t)row*192 + ug]  = hn;
                hs[((size_t)row*Lc + tt)*384 + d*192 + ug] = hn;
            }
        }
    }
}

// ---------------- convT1d gather-GEMM + bias + residual  (M128N64) ----------------
__global__ void __launch_bounds__(256, 2) convt_gemm(int phase, const float* __restrict__ Tb,
                                                     const float* __restrict__ x0, const float* __restrict__ x1)
{
    extern __shared__ uint32_t smemu[];
    uint32_t* sA = smemu;
    uint32_t* sB = smemu + 2*4608;
    int s = blockIdx.z;
    int Lc   = phase ? L1 : L0;
    int Qlen = phase ? 512 : 65;
    const float* hs = g_hseq + (size_t)s*HS_S;
    const float* Bw = g_twt + (size_t)(phase*2 + s)*1536*48;
    int row0 = blockIdx.y*128;
    int tid = threadIdx.x;
    WARP_IDS
    float acc[2][4][4] = {};

    #define CONV_LOAD(buf, kcc) { \
        int ktap = (kcc) / 384; \
        int i0 = (kcc) - ktap*384; \
        _Pragma("unroll") for (int rep = 0; rep < 4; ++rep) { \
            int idx = tid + rep*256; \
            int rr = idx >> 3, seg = idx & 7; \
            int gr = row0 + rr; \
            int n = gr / Qlen, q = gr - n*Qlen; \
            int l = q - ktap; \
            bool val = (l >= 0 && l < Lc); \
            const float* src = val ? &hs[((size_t)n*Lc + l)*384 + i0 + seg*4] : hs; \
            cp16z(&ASI(buf,rr,seg*4), src, val); } \
        _Pragma("unroll") for (int rep = 0; rep < 2; ++rep) { \
            int idx = tid + rep*256; \
            int k = idx >> 4, seg = idx & 15; \
            bool val = (seg*4 < 48); \
            const float* src = val ? &Bw[(size_t)((kcc) + k)*48 + seg*4] : Bw; \
            cp16z(&BN64(buf,k,seg*4), src, val); } }

    CONV_LOAD(0, 0)
    cp_commit();
    for (int c = 0; c < 48; ++c) {
        int cur = c & 1;
        if (c < 47) {
            CONV_LOAD(cur^1, (c+1)*32)
            cp_commit();
            cp_wait1();
        } else cp_wait0();
        __syncthreads();
        MMA_N64(cur)
        __syncthreads();
    }
    #undef CONV_LOAD
    int g = phase*2 + s;
    #pragma unroll
    for (int mt = 0; mt < 2; ++mt) {
        int rbase = row0 + wm*32 + mt*16 + gp;
        #pragma unroll
        for (int nt = 0; nt < 4; ++nt) {
            int cb = wn*32 + nt*8 + 2*qn;
            #pragma unroll
            for (int half = 0; half < 2; ++half) {
                int row = rbase + half*8;
                int n = row / Qlen, q = row - n*Qlen;
                #pragma unroll
                for (int j = 0; j < 2; ++j) {
                    int c = cb + j;
                    if (c < 48) {
                        float v = acc[mt][nt][half*2 + j] + Tb[g*48 + c];
                        if (phase == 0) {
                            int b = n >> 9, tpos = n & 511;
                            size_t oi = ((size_t)(b*48 + c)*512 + tpos)*65 + q;
                            const float* res = s ? x1 : x0;
                            g_io[(size_t)s*TSZ + oi] = v + res[oi];
                        } else {
                            int b = n / 65, f = n - b*65;
                            size_t oi = ((size_t)(b*48 + c)*512 + q)*65 + f;
                            g_eo[(size_t)s*TSZ + oi] = v + g_io[(size_t)s*TSZ + oi];
                        }
                    }
                }
            }
        }
    }
}

// ---------------- q/k/v head projections + leaky + LN (K written transposed) ----------------
__global__ void __launch_bounds__(256) qkv_kernel(
    const float* __restrict__ AWqk, const float* __restrict__ Abqk, const float* __restrict__ Aaqk,
    const float* __restrict__ Agqk, const float* __restrict__ Abgqk,
    const float* __restrict__ AWv,  const float* __restrict__ Abv,  const float* __restrict__ Aav,
    const float* __restrict__ Agv,  const float* __restrict__ Abgv)
{
    int t = blockIdx.x, b = blockIdx.y, s = blockIdx.z, tid = threadIdx.x;
    int lane = tid & 31, warp = tid >> 5;
    __shared__ float zs[3120];
    __shared__ float buf[780];
    __shared__ float red[32];
    const float* z = g_eo + (size_t)s*TSZ;
    for (int i = tid; i < 3120; i += 256) {
        int c = i / 65, f = i - c*65;
        zs[i] = z[((size_t)(b*48 + c)*512 + t)*65 + f];
    }
    __syncthreads();
    for (int grp = 0; grp < 12; ++grp) {
        int tensor = grp >> 2, h = grp & 3;
        int nvals;
        const float *W, *bb, *gam, *bet;
        float alpha;
        if (tensor < 2) {
            nvals = 520;
            int hh = (s*2 + tensor)*4 + h;
            W = AWqk + (size_t)hh*8*48; bb = Abqk + hh*8; alpha = Aaqk[hh];
            gam = Agqk + (size_t)hh*8*65; bet = Abgqk + (size_t)hh*8*65;
        } else {
            nvals = 780;
            int hh = s*4 + h;
            W = AWv + (size_t)hh*12*48; bb = Abv + hh*12; alpha = Aav[hh];
            gam = Agv + (size_t)hh*12*65; bet = Abgv + (size_t)hh*12*65;
        }
        float ls = 0.f, lq = 0.f;
        for (int idx = tid; idx < nvals; idx += 256) {
            int e = idx / 65, f = idx - e*65;
            float a = bb[e];
            const float* wr = W + e*48;
            #pragma unroll
            for (int c = 0; c < 48; ++c) a += zs[c*65 + f]*wr[c];
            a = a >= 0.f ? a : alpha*a;
            buf[idx] = a; ls += a; lq += a*a;
        }
        #pragma unroll
        for (int o = 16; o; o >>= 1) {
            ls += __shfl_xor_sync(0xffffffffu, ls, o);
            lq += __shfl_xor_sync(0xffffffffu, lq, o);
        }
        if (lane == 0) { red[warp] = ls; red[8 + warp] = lq; }
        __syncthreads();
        if (tid == 0) {
            float a = 0.f, c = 0.f;
            #pragma unroll
            for (int i = 0; i < 8; ++i) { a += red[i]; c += red[8 + i]; }
            red[16] = a; red[17] = c;
        }
        __syncthreads();
        float mu = red[16] / nvals;
        float inv = rsqrtf(red[17] / nvals - mu*mu + EPSLN);
        int bz = s*16 + b*4 + h;
        if (tensor == 0) {
            float* outp = g_q + ((size_t)bz*512 + t)*EK2;
            for (int idx = tid; idx < nvals; idx += 256)
                outp[idx] = (buf[idx] - mu)*inv*gam[idx] + bet[idx];
            if (tid < EK2 - 520) outp[520 + tid] = 0.f;
        } else if (tensor == 1) {
            float* outp = g_k + (size_t)bz*EK2*512;
            for (int idx = tid; idx < nvals; idx += 256)
                outp[(size_t)idx*512 + t] = (buf[idx] - mu)*inv*gam[idx] + bet[idx];
            if (tid < EK2 - 520) outp[(size_t)(520 + tid)*512 + t] = 0.f;
        } else {
            float* outp = g_v + ((size_t)bz*512 + t)*780;
            for (int idx = tid; idx < nvals; idx += 256)
                outp[idx] = (buf[idx] - mu)*inv*gam[idx] + bet[idx];
        }
        __syncthreads();
    }
}

// ---------------- QK^T (scaled, XL) ----------------
__global__ void __launch_bounds__(256, 2) qk_gemm()
{
    extern __shared__ uint32_t smemu[];
    uint32_t* sA = smemu;
    uint32_t* sB = smemu + 2*4608;
    int bz = blockIdx.z;
    const float* Q  = g_q + (size_t)bz*512*EK2;
    const float* Kt = g_k + (size_t)bz*EK2*512;
    float* Co = g_attn + (size_t)bz*512*512;
    int row0 = blockIdx.y*128, col0 = blockIdx.x*128;
    int tid = threadIdx.x;
    WARP_IDS
    float acc[2][8][4] = {};
    LOAD_A128(0, Q, EK2, 511, 0)
    LOAD_BXL(0, Kt, 512, 0)
    cp_commit();
    for (int c = 0; c < 17; ++c) {
        int cur = c & 1;
        if (c < 16) {
            LOAD_A128(cur^1, Q, EK2, 511, (c+1)*32)
            LOAD_BXL(cur^1, Kt, 512, (c+1)*32)
            cp_commit();
            cp_wait1();
        } else cp_wait0();
        __syncthreads();
        MMA_XL(cur)
        __syncthreads();
    }
    float rs = rsqrtf(520.f);
    #pragma unroll
    for (int mt = 0; mt < 2; ++mt) {
        int r = row0 + wm*32 + mt*16 + gp;
        #pragma unroll
        for (int nt = 0; nt < 8; ++nt) {
            int cb = col0 + wn*64 + nt*8 + 2*qn;
            *(float2*)&Co[(size_t)r*512 + cb]     = make_float2(acc[mt][nt][0]*rs, acc[mt][nt][1]*rs);
            *(float2*)&Co[(size_t)(r+8)*512 + cb] = make_float2(acc[mt][nt][2]*rs, acc[mt][nt][3]*rs);
        }
    }
}

// ---------------- row softmax ----------------
__global__ void __launch_bounds__(256) softmax_rows()
{
    int row = blockIdx.x, bz = blockIdx.y, tid = threadIdx.x;
    float* p = g_attn + (size_t)bz*512*512 + (size_t)row*512;
    __shared__ float sm[512];
    __shared__ float red[256];
    sm[tid] = p[tid]; sm[tid + 256] = p[tid + 256];
    red[tid] = fmaxf(sm[tid], sm[tid + 256]);
    __syncthreads();
    for (int st = 128; st > 0; st >>= 1) {
        if (tid < st) red[tid] = fmaxf(red[tid], red[tid + st]);
        __syncthreads();
    }
    float mx = red[0];
    __syncthreads();
    float e0 = expf(sm[tid] - mx), e1 = expf(sm[tid + 256] - mx);
    red[tid] = e0 + e1;
    __syncthreads();
    for (int st = 128; st > 0; st >>= 1) {
        if (tid < st) red[tid] += red[tid + st];
        __syncthreads();
    }
    float invs = 1.f / red[0];
    p[tid] = e0*invs; p[tid + 256] = e1*invs;
}

// ---------------- P @ V (XL) ----------------
__global__ void __launch_bounds__(256, 2) pv_gemm()
{
    extern __shared__ uint32_t smemu[];
    uint32_t* sA = smemu;
    uint32_t* sB = smemu + 2*4608;
    int bz = blockIdx.z;
    const float* A  = g_attn + (size_t)bz*512*512;
    const float* Bv = g_v + (size_t)bz*512*780;
    float* Co = g_av + (size_t)bz*512*780;
    int row0 = blockIdx.y*128, col0 = blockIdx.x*128;
    int tid = threadIdx.x;
    WARP_IDS
    float acc[2][8][4] = {};
    LOAD_A128(0, A, 512, 511, 0)
    LOAD_BXL_G(0, Bv, 780, 0, 780)
    cp_commit();
    for (int c = 0; c < 16; ++c) {
        int cur = c & 1;
        if (c < 15) {
            LOAD_A128(cur^1, A, 512, 511, (c+1)*32)
            LOAD_BXL_G(cur^1, Bv, 780, (c+1)*32, 780)
            cp_commit();
            cp_wait1();
        } else cp_wait0();
        __syncthreads();
        MMA_XL(cur)
        __syncthreads();
    }
    #pragma unroll
    for (int mt = 0; mt < 2; ++mt) {
        int r = row0 + wm*32 + mt*16 + gp;
        #pragma unroll
        for (int nt = 0; nt < 8; ++nt) {
            int cb = col0 + wn*64 + nt*8 + 2*qn;
            #pragma unroll
            for (int j = 0; j < 2; ++j) {
                int col = cb + j;
                if (col < 780) {
                    Co[(size_t)r*780 + col]     = acc[mt][nt][j];
                    Co[(size_t)(r+8)*780 + col] = acc[mt][nt][2 + j];
                }
            }
        }
    }
}

// ---------------- output projection + leaky + LN + residual ----------------
__global__ void __launch_bounds__(256) outproj_kernel(
    const float* __restrict__ AWp, const float* __restrict__ Abp, const float* __restrict__ Aap,
    const float* __restrict__ Agp, const float* __restrict__ Abgp, float* __restrict__ dout)
{
    int t = blockIdx.x, b = blockIdx.y, s = blockIdx.z, tid = threadIdx.x;
    int lane = tid & 31, warp = tid >> 5;
    __shared__ float os[3120];
    __shared__ float buf[3120];
    __shared__ float red[32];
    for (int i = tid; i < 3120; i += 256) {
        int c = i / 65, f = i - c*65;
        int h = c / 12, dv = c - h*12;
        os[i] = g_av[((size_t)((s*16 + b*4 + h)*512) + t)*780 + dv*65 + f];
    }
    __syncthreads();
    float alpha = Aap[s];
    float ls = 0.f, lq = 0.f;
    for (int idx = tid; idx < 3120; idx += 256) {
        int o = idx / 65, f = idx - o*65;
        float a = Abp[s*48 + o];
        const float* wr = AWp + (size_t)(s*48 + o)*48;
        #pragma unroll
        for (int c = 0; c < 48; ++c) a += os[c*65 + f]*wr[c];
        a = a >= 0.f ? a : alpha*a;
        buf[idx] = a; ls += a; lq += a*a;
    }
    #pragma unroll
    for (int o = 16; o; o >>= 1) {
        ls += __shfl_xor_sync(0xffffffffu, ls, o);
        lq += __shfl_xor_sync(0xffffffffu, lq, o);
    }
    if (lane == 0) { red[warp] = ls; red[8 + warp] = lq; }
    __syncthreads();
    if (tid == 0) {
        float a = 0.f, c = 0.f;
        #pragma unroll
        for (int i = 0; i < 8; ++i) { a += red[i]; c += red[8 + i]; }
        red[16] = a; red[17] = c;
    }
    __syncthreads();
    float mu = red[16] / 3120.f;
    float inv = rsqrtf(red[17] / 3120.f - mu*mu + EPSLN);
    for (int idx = tid; idx < 3120; idx += 256) {
        int o = idx / 65, f = idx - o*65;
        float v = (buf[idx] - mu)*inv*Agp[(s*48 + o)*65 + f] + Abgp[(s*48 + o)*65 + f]
                + g_eo[(size_t)s*TSZ + ((size_t)(b*48 + o)*512 + t)*65 + f];
        dout[(((size_t)(s*4 + b)*48 + o)*512 + t)*65 + f] = v;
    }
}

// ---------------- host launch ----------------
extern "C" void kernel_launch(void* const* d_in, const int* in_sizes, int n_in,
                              void* d_out, int out_size)
{
    const float* x     = (const float*)d_in[0];
    const float* c2    = (const float*)d_in[1];
    const float* ng    = (const float*)d_in[2];
    const float* nb    = (const float*)d_in[3];
    const float* LWih  = (const float*)d_in[4];
    const float* LWhh  = (const float*)d_in[5];
    const float* Lb    = (const float*)d_in[6];
    const float* TW    = (const float*)d_in[7];
    const float* Tb    = (const float*)d_in[8];
    const float* AWqk  = (const float*)d_in[9];
    const float* Abqk  = (const float*)d_in[10];
    const float* Aaqk  = (const float*)d_in[11];
    const float* Agqk  = (const float*)d_in[12];
    const float* Abgqk = (const float*)d_in[13];
    const float* AWv   = (const float*)d_in[14];
    const float* Abv   = (const float*)d_in[15];
    const float* Aav   = (const float*)d_in[16];
    const float* Agv   = (const float*)d_in[17];
    const float* Abgv  = (const float*)d_in[18];
    const float* AWp   = (const float*)d_in[19];
    const float* Abp   = (const float*)d_in[20];
    const float* Aap   = (const float*)d_in[21];
    const float* Agp   = (const float*)d_in[22];
    const float* Abgp  = (const float*)d_in[23];
    float* out = (float*)d_out;

    cudaFuncSetAttribute(xw_gemm,       cudaFuncAttributeMaxDynamicSharedMemorySize, SMEM_XXL);
    cudaFuncSetAttribute(lstm_step_big, cudaFuncAttributeMaxDynamicSharedMemorySize, SMEM_LBIG);
    cudaFuncSetAttribute(qk_gemm,       cudaFuncAttributeMaxDynamicSharedMemorySize, SMEM_XL);
    cudaFuncSetAttribute(pv_gemm,       cudaFuncAttributeMaxDynamicSharedMemorySize, SMEM_XL);
    cudaFuncSetAttribute(lstm_step,     cudaFuncAttributeMaxDynamicSharedMemorySize, SMEM_N64);
    cudaFuncSetAttribute(convt_gemm,    cudaFuncAttributeMaxDynamicSharedMemorySize, SMEM_N64);

    pack_weights<<<512, 256>>>(LWih, LWhh, Lb, TW);

    // ---- phase 0: intra ----
    zero_state<<<512, 256>>>();
    ln_unfold_intra<<<dim3(512, 4, 2), 256>>>(x, c2, ng, nb);
    xw_gemm<<<dim3(3, (ROWS0 + 127)/128, 4), 256, SMEM_XXL>>>(0, ROWS0);
    for (int t = 0; t < L0; ++t)
        lstm_step_big<<<dim3(3, 32, 4), 256, SMEM_LBIG>>>(t, t & 1);
    convt_gemm<<<dim3(1, CONV_ROWS/128, 2), 256, SMEM_N64>>>(0, Tb, x, c2);

    // ---- phase 1: inter ----
    zero_state<<<512, 256>>>();
    ln_unfold_inter<<<dim3(512, 4, 2), 256>>>(ng, nb);
    xw_gemm<<<dim3(3, (ROWS1 + 127)/128, 4), 256, SMEM_XXL>>>(1, ROWS1);
    for (int t = 0; t < L1; ++t)
        lstm_step<<<dim3(12, (N1 + 127)/128, 4), 256, SMEM_N64>>>(t, 1, t & 1, N1, L1);
    convt_gemm<<<dim3(1, CONV_ROWS/128, 2), 256, SMEM_N64>>>(1, Tb, x, c2);

    // ---- attention ----
    qkv_kernel<<<dim3(512, 4, 2), 256>>>(AWqk, Abqk, Aaqk, Agqk, Abgqk,
                                         AWv, Abv, Aav, Agv, Abgv);
    qk_gemm<<<dim3(4, 4, 32), 256, SMEM_XL>>>();
    softmax_rows<<<dim3(512, 32), 256>>>();
    pv_gemm<<<dim3(7, 4, 32), 256, SMEM_XL>>>();
    outproj_kernel<<<dim3(512, 4, 2), 256>>>(AWp, Abp, Aap, Agp, Abgp, out);
}

// round 14
// speedup vs baseline: 1.3329x; 1.1836x over previous
#include <cuda_runtime.h>
#include <cuda_fp16.h>
#include <math.h>
#include <stdint.h>

// ---------------- constants ----------------
#define Bb 4
#define Cc 48
#define Tt 512
#define Ff 65
#define L0 62
#define L1 509
#define N0 2048
#define N1 260
#define ROWS0 126976
#define ROWS1 132340
#define ROWSMAX 132340
#define CONV_ROWS 133120
#define XU_S  ((size_t)ROWSMAX*192)
#define XW_S  ((size_t)ROWSMAX*768)
#define HS_S  ((size_t)ROWSMAX*384)
#define TSZ   (Bb*Cc*Tt*Ff)
#define EK2   544
#define EPSLN 1e-5f

#define SMEM_XL   ((2*128*36 + 2*32*136)*4)   // 71680  (qk/pv tf32)
#define SMEM_H128 ((2*128*20 + 2*16*136)*4)   // 37888  (xw fp16)
#define SMEM_H64  ((2*128*20 + 2*16*72)*4)    // 29696  (lstm/convt fp16)

// ---------------- device scratch ----------------
__device__ __half g_xu[2*XU_S];
__device__ float  g_xw[4*XW_S];
__device__ __half g_hseq[2*HS_S];
__device__ __half g_h[2*4*2048*192];
__device__ float  g_c[4*2048*192];
__device__ uint32_t g_wihp2[8*96*768];   // [w][j2][col]  packed (2j2,2j2+1)
__device__ uint32_t g_whhp2[8*96*768];
__device__ float  g_bp[8*768];
__device__ uint32_t g_twt2[4*768*48];    // [g][k2][o]
__device__ float  g_io[2*TSZ];
__device__ float  g_eo[2*TSZ];
__device__ float  g_q[(size_t)2*16*512*EK2];
__device__ float  g_k[(size_t)2*16*EK2*512];   // [bz][k][t]
__device__ float  g_v[2*16*512*780];
__device__ float  g_attn[(size_t)2*16*512*512];
__device__ float  g_av[2*16*512*780];

__device__ __forceinline__ float sigf(float x){ return 1.f/(1.f+expf(-x)); }

__device__ __forceinline__ void mma_tf32(float* c, uint32_t a0, uint32_t a1,
                                         uint32_t a2, uint32_t a3,
                                         uint32_t b0, uint32_t b1){
    asm volatile("mma.sync.aligned.m16n8k8.row.col.f32.tf32.tf32.f32 "
        "{%0,%1,%2,%3}, {%4,%5,%6,%7}, {%8,%9}, {%0,%1,%2,%3};"
        : "+f"(c[0]), "+f"(c[1]), "+f"(c[2]), "+f"(c[3])
        : "r"(a0), "r"(a1), "r"(a2), "r"(a3), "r"(b0), "r"(b1));
}

__device__ __forceinline__ void mma_f16(float* c, uint32_t a0, uint32_t a1,
                                        uint32_t a2, uint32_t a3,
                                        uint32_t b0, uint32_t b1){
    asm volatile("mma.sync.aligned.m16n8k16.row.col.f32.f16.f16.f32 "
        "{%0,%1,%2,%3}, {%4,%5,%6,%7}, {%8,%9}, {%0,%1,%2,%3};"
        : "+f"(c[0]), "+f"(c[1]), "+f"(c[2]), "+f"(c[3])
        : "r"(a0), "r"(a1), "r"(a2), "r"(a3), "r"(b0), "r"(b1));
}

// cp.async helpers
__device__ __forceinline__ void cp16(void* smem, const void* gmem){
    uint32_t s = (uint32_t)__cvta_generic_to_shared(smem);
    asm volatile("cp.async.ca.shared.global [%0], [%1], 16;\n" :: "r"(s), "l"(gmem) : "memory");
}
__device__ __forceinline__ void cp16z(void* smem, const void* gmem, bool valid){
    uint32_t s = (uint32_t)__cvta_generic_to_shared(smem);
    int sz = valid ? 16 : 0;
    asm volatile("cp.async.ca.shared.global [%0], [%1], 16, %2;\n" :: "r"(s), "l"(gmem), "r"(sz) : "memory");
}
__device__ __forceinline__ void cp_commit(){ asm volatile("cp.async.commit_group;\n" ::: "memory"); }
__device__ __forceinline__ void cp_wait0(){ asm volatile("cp.async.wait_group 0;\n" ::: "memory"); }
__device__ __forceinline__ void cp_wait1(){ asm volatile("cp.async.wait_group 1;\n" ::: "memory"); }

// ------------- shared tile indexing -------------
// tf32 (qk/pv): sA [2][16][72]-style as before
#define ASI(buf,m,k)  sA[(buf)*4608 + (m)*36 + (k)]
#define BXL(buf,k,n)  sB[(buf)*4352 + (k)*136 + (n)]
// fp16: A [2][128][20] u32 (each word = 2 halves along k); B [2][16][pitch]
#define AH(buf,m,k2)    sA[(buf)*2560 + (m)*20 + (k2)]
#define BH64(buf,k2,n)  sB[(buf)*1152 + (k2)*72 + (n)]
#define BH128(buf,k2,n) sB[(buf)*2176 + (k2)*136 + (n)]

#define WARP_IDS \
    int lane = tid & 31, warp = tid >> 5; \
    int wm = warp >> 1, wn = warp & 1;    \
    int gp = lane >> 2, qn = lane & 3;

// ---- fp16 A stage: 128 rows x 32 halves (16 words), A half* row-major lda=192 ----
#define LOAD_AH128(buf, Aptr, rowClamp, kcc) { \
    _Pragma("unroll") for (int rep = 0; rep < 2; ++rep) { \
        int idx = tid + rep*256; \
        int row = idx >> 2, seg = idx & 3; \
        int gr = row0 + row; if (gr > (rowClamp)) gr = (rowClamp); \
        cp16(&AH(buf,row,seg*4), &(Aptr)[(size_t)gr*192 + (kcc) + seg*8]); } }

// ---- fp16 B stage from packed uint32 weights [j2][768]: 16 j2 x 64 cols ----
#define LOAD_BH64(buf, Bptr, kcc2) { \
    int k = tid >> 4, seg = tid & 15; \
    cp16(&BH64(buf,k,seg*4), &(Bptr)[(size_t)((kcc2)+k)*768 + col0 + seg*4]); }

// ---- fp16 B stage 128 cols ----
#define LOAD_BH128(buf, Bptr, kcc2) { \
    _Pragma("unroll") for (int rep = 0; rep < 2; ++rep) { \
        int idx = tid + rep*256; \
        int k = idx >> 5, seg = idx & 31; \
        cp16(&BH128(buf,k,seg*4), &(Bptr)[(size_t)((kcc2)+k)*768 + col0 + seg*4]); } }

// ---- fp16 mma, warp tile 32x64, B pitch 136 (xw) : acc[2][8][4] ----
#define MMA_H_XL(buf) \
    _Pragma("unroll") for (int ks = 0; ks < 2; ++ks) { \
        int kq = ks*8 + qn; \
        int am0 = wm*32 + gp; \
        uint32_t a00=AH(buf,am0,kq),    a01=AH(buf,am0+8,kq); \
        uint32_t a02=AH(buf,am0,kq+4),  a03=AH(buf,am0+8,kq+4); \
        uint32_t a10=AH(buf,am0+16,kq),   a11=AH(buf,am0+24,kq); \
        uint32_t a12=AH(buf,am0+16,kq+4), a13=AH(buf,am0+24,kq+4); \
        int bn = wn*64 + gp; \
        _Pragma("unroll") for (int nt = 0; nt < 8; ++nt) { \
            uint32_t b0 = BH128(buf,kq,bn+nt*8), b1 = BH128(buf,kq+4,bn+nt*8); \
            mma_f16(acc[0][nt], a00,a01,a02,a03, b0,b1); \
            mma_f16(acc[1][nt], a10,a11,a12,a13, b0,b1); } }

// ---- fp16 mma, warp tile 32x32, B pitch 72 (lstm/convt) : acc[2][4][4] ----
#define MMA_H_N64(buf) \
    _Pragma("unroll") for (int ks = 0; ks < 2; ++ks) { \
        int kq = ks*8 + qn; \
        int am0 = wm*32 + gp; \
        uint32_t a00=AH(buf,am0,kq),    a01=AH(buf,am0+8,kq); \
        uint32_t a02=AH(buf,am0,kq+4),  a03=AH(buf,am0+8,kq+4); \
        uint32_t a10=AH(buf,am0+16,kq),   a11=AH(buf,am0+24,kq); \
        uint32_t a12=AH(buf,am0+16,kq+4), a13=AH(buf,am0+24,kq+4); \
        int bn = wn*32 + gp; \
        _Pragma("unroll") for (int nt = 0; nt < 4; ++nt) { \
            uint32_t b0 = BH64(buf,kq,bn+nt*8), b1 = BH64(buf,kq+4,bn+nt*8); \
            mma_f16(acc[0][nt], a00,a01,a02,a03, b0,b1); \
            mma_f16(acc[1][nt], a10,a11,a12,a13, b0,b1); } }

// ---- tf32 staging/mma for qk/pv (unchanged from R11) ----
#define LOAD_A_TRANS(Aptr, lda, rowClamp) { \
    int aRow = tid >> 2, ak = (tid & 3)*4; \
    int gr = row0 + aRow; if (gr > (rowClamp)) gr = (rowClamp); \
    float4 v = *(const float4*)&(Aptr)[(size_t)gr*(lda) + kc + ak]; \
    As[ak  ][aRow] = __float_as_uint(v.x); As[ak+1][aRow] = __float_as_uint(v.y); \
    As[ak+2][aRow] = __float_as_uint(v.z); As[ak+3][aRow] = __float_as_uint(v.w); }

#define LOAD_A128F(buf, Aptr, lda, rowClamp, kcc) { \
    _Pragma("unroll") for (int rep = 0; rep < 4; ++rep) { \
        int idx = tid + rep*256; \
        int row = idx >> 3, seg = idx & 7; \
        int gr = row0 + row; if (gr > (rowClamp)) gr = (rowClamp); \
        cp16(&sA[(buf)*4608 + row*36 + seg*4], &(Aptr)[(size_t)gr*(lda) + (kcc) + seg*4]); } }

#define LOAD_BXLF(buf, Bptr, ldb, kcc) { \
    _Pragma("unroll") for (int rep = 0; rep < 4; ++rep) { \
        int idx = tid + rep*256; \
        int k = idx >> 5, seg = idx & 31; \
        cp16(&BXL(buf,k,seg*4), &(Bptr)[(size_t)((kcc) + k)*(ldb) + col0 + seg*4]); } }

#define LOAD_BXLF_G(buf, Bptr, ldb, kcc, Ncols) { \
    _Pragma("unroll") for (int rep = 0; rep < 4; ++rep) { \
        int idx = tid + rep*256; \
        int k = idx >> 5, seg = idx & 31; \
        int cc = col0 + seg*4; \
        bool val = (cc < (Ncols)); \
        const float* src = val ? &(Bptr)[(size_t)((kcc) + k)*(ldb) + cc] : (const float*)(Bptr); \
        cp16z(&BXL(buf,k,seg*4), src, val); } }

#define ASIF(buf,m,k) sA[(buf)*4608 + (m)*36 + (k)]
#define MMA_XLF(buf) \
    _Pragma("unroll") for (int k8 = 0; k8 < 4; ++k8) { \
        int kb = k8*8 + qn; \
        int am0 = wm*32 + gp; \
        uint32_t a00=ASIF(buf,am0,kb),    a01=ASIF(buf,am0+8,kb); \
        uint32_t a02=ASIF(buf,am0,kb+4),  a03=ASIF(buf,am0+8,kb+4); \
        uint32_t a10=ASIF(buf,am0+16,kb),   a11=ASIF(buf,am0+24,kb); \
        uint32_t a12=ASIF(buf,am0+16,kb+4), a13=ASIF(buf,am0+24,kb+4); \
        int bn = wn*64 + gp; \
        _Pragma("unroll") for (int nt = 0; nt < 8; ++nt) { \
            uint32_t b0 = BXL(buf,kb,bn+nt*8), b1 = BXL(buf,kb+4,bn+nt*8); \
            mma_tf32(acc[0][nt], a00,a01,a02,a03, b0,b1); \
            mma_tf32(acc[1][nt], a10,a11,a12,a13, b0,b1); } }

// ---------------- weight packing (fp16 pair-packed along k) ----------------
__global__ void pack_weights(const float* __restrict__ LWih, const float* __restrict__ LWhh,
                             const float* __restrict__ Lb,   const float* __restrict__ TW)
{
    int stride = gridDim.x * blockDim.x;
    int t0 = blockIdx.x * blockDim.x + threadIdx.x;
    for (int idx = t0; idx < 8*96*768; idx += stride) {
        int w = idx / (96*768);
        int r = idx - w*(96*768);
        int j2 = r / 768, col = r - j2*768;
        int u = col >> 2, gt = col & 3;
        int g = (w>>2)*2 + ((w>>1)&1);
        int d = w & 1;
        size_t src = ((size_t)(g*2+d)*768 + gt*192 + u);
        __half2 hi = __floats2half2_rn(LWih[src*192 + 2*j2], LWih[src*192 + 2*j2 + 1]);
        __half2 hh = __floats2half2_rn(LWhh[src*192 + 2*j2], LWhh[src*192 + 2*j2 + 1]);
        g_wihp2[idx] = *(uint32_t*)&hi;
        g_whhp2[idx] = *(uint32_t*)&hh;
    }
    for (int idx = t0; idx < 8*768; idx += stride) {
        int w = idx / 768, col = idx - w*768;
        int u = col >> 2, gt = col & 3;
        int g = (w>>2)*2 + ((w>>1)&1);
        int d = w & 1;
        g_bp[idx] = Lb[(g*2+d)*768 + gt*192 + u];
    }
    for (int idx = t0; idx < 4*768*48; idx += stride) {
        int g = idx / (768*48);
        int r = idx - g*(768*48);
        int k2 = r / 48, o = r - k2*48;
        int kk = 2*k2;
        int k = kk / 384, i = kk - k*384;
        __half2 tv = __floats2half2_rn(
            TW[(((size_t)g*384 + i  )*48 + o)*4 + k],
            TW[(((size_t)g*384 + i+1)*48 + o)*4 + k]);
        g_twt2[idx] = *(uint32_t*)&tv;
    }
}

__global__ void zero_state()
{
    int stride = gridDim.x * blockDim.x;
    int t0 = blockIdx.x * blockDim.x + threadIdx.x;
    uint32_t* hz = (uint32_t*)g_h;
    for (int i = t0; i < 4*2048*192; i += stride) hz[i] = 0;   // 2*4*2048*192 halves / 2
    for (int i = t0; i < 4*2048*192; i += stride) g_c[i] = 0.f;
}

// ---------------- LN over C + unfold, intra ----------------
__global__ void ln_unfold_intra(const float* __restrict__ x0, const float* __restrict__ x1,
                                const float* __restrict__ ng, const float* __restrict__ nb)
{
    int t = blockIdx.x, b = blockIdx.y, s = blockIdx.z;
    const float* src = s ? x1 : x0;
    __shared__ float zs[48*65];
    __shared__ float mu[65], inv[65];
    int tid = threadIdx.x;
    for (int i = tid; i < 48*65; i += 256) {
        int c = i / 65, f = i - c*65;
        zs[i] = src[((size_t)(b*48 + c)*512 + t)*65 + f];
    }
    __syncthreads();
    if (tid < 65) {
        float s1 = 0.f, s2 = 0.f;
        #pragma unroll
        for (int c = 0; c < 48; ++c) { float v = zs[c*65 + tid]; s1 += v; s2 += v*v; }
        float m = s1 * (1.f/48.f);
        mu[tid] = m;
        inv[tid] = rsqrtf(s2*(1.f/48.f) - m*m + EPSLN);
    }
    __syncthreads();
    size_t n = (size_t)b*512 + t;
    __half* outp = g_xu + (size_t)s*XU_S + n*(size_t)L0*192;
    for (int i = tid; i < 48*L0*4; i += 256) {
        int c = i / (L0*4);
        int r = i - c*(L0*4);
        int l = r >> 2, k = r & 3;
        int q = l + k;
        float v = (zs[c*65 + q] - mu[q]) * inv[q] * ng[s*48 + c] + nb[s*48 + c];
        outp[(size_t)l*192 + c*4 + k] = __float2half(v);
    }
}

// ---------------- LN over C + unfold, inter ----------------
__global__ void ln_unfold_inter(const float* __restrict__ ng, const float* __restrict__ nb)
{
    int t = blockIdx.x, b = blockIdx.y, s = blockIdx.z;
    const float* src = g_io + (size_t)s*TSZ;
    __shared__ float zs[48*65];
    __shared__ float mu[65], inv[65];
    int tid = threadIdx.x;
    for (int i = tid; i < 48*65; i += 256) {
        int c = i / 65, f = i - c*65;
        zs[i] = src[((size_t)(b*48 + c)*512 + t)*65 + f];
    }
    __syncthreads();
    if (tid < 65) {
        float s1 = 0.f, s2 = 0.f;
        #pragma unroll
        for (int c = 0; c < 48; ++c) { float v = zs[c*65 + tid]; s1 += v; s2 += v*v; }
        float m = s1 * (1.f/48.f);
        mu[tid] = m;
        inv[tid] = rsqrtf(s2*(1.f/48.f) - m*m + EPSLN);
    }
    __syncthreads();
    int gi = 2 + s;
    for (int i = tid; i < 48*65; i += 256) {
        int c = i / 65, f = i - c*65;
        float v = (zs[i] - mu[f]) * inv[f] * ng[gi*48 + c] + nb[gi*48 + c];
        size_t n = (size_t)b*65 + f;
        __half* outp = g_xu + (size_t)s*XU_S + n*(size_t)L1*192;
        __half hv = __float2half(v);
        #pragma unroll
        for (int k = 0; k < 4; ++k) {
            int l = t - k;
            if (l >= 0 && l < L1) outp[(size_t)l*192 + c*4 + k] = hv;
        }
    }
}

// ---------------- xw = xu @ Wih^T + b  (fp16 mma, 128x128) ----------------
__global__ void __launch_bounds__(256, 2) xw_gemm(int phase, int M)
{
    extern __shared__ uint32_t smemu[];
    uint32_t* sA = smemu;              // [2][128][20]
    uint32_t* sB = smemu + 2*2560;     // [2][16][136]
    int combo = blockIdx.z;
    int s = combo >> 1;
    const __half* A      = g_xu + (size_t)s*XU_S;
    const uint32_t* Bw   = g_wihp2 + (size_t)(phase*4 + combo)*96*768;
    const float* bias    = g_bp + (size_t)(phase*4 + combo)*768;
    float* Co = g_xw + (size_t)combo*XW_S;
    int row0 = blockIdx.y*128, col0 = blockIdx.x*128;
    int tid = threadIdx.x;
    WARP_IDS
    float acc[2][8][4] = {};
    LOAD_AH128(0, A, M-1, 0)
    LOAD_BH128(0, Bw, 0)
    cp_commit();
    #pragma unroll
    for (int c = 0; c < 6; ++c) {
        int cur = c & 1;
        if (c < 5) {
            LOAD_AH128(cur^1, A, M-1, (c+1)*32)
            LOAD_BH128(cur^1, Bw, (c+1)*16)
            cp_commit();
            cp_wait1();
        } else cp_wait0();
        __syncthreads();
        MMA_H_XL(cur)
        __syncthreads();
    }
    #pragma unroll
    for (int mt = 0; mt < 2; ++mt) {
        int r = row0 + wm*32 + mt*16 + gp;
        #pragma unroll
        for (int nt = 0; nt < 8; ++nt) {
            int cb = col0 + wn*64 + nt*8 + 2*qn;
            float b0v = bias[cb], b1v = bias[cb+1];
            if (r < M)
                *(float2*)&Co[(size_t)r*768 + cb] = make_float2(acc[mt][nt][0]+b0v, acc[mt][nt][1]+b1v);
            if (r + 8 < M)
                *(float2*)&Co[(size_t)(r+8)*768 + cb] = make_float2(acc[mt][nt][2]+b0v, acc[mt][nt][3]+b1v);
        }
    }
}

// ---------------- fused LSTM step (fp16 mma, 128x64, shfl gate epilogue) ----------------
__global__ void __launch_bounds__(256, 2) lstm_step(int t, int phase, int parity, int Nseq, int Lc)
{
    extern __shared__ uint32_t smemu[];
    uint32_t* sA = smemu;              // [2][128][20]
    uint32_t* sB = smemu + 2*2560;     // [2][16][72]
    int combo = blockIdx.z;
    int s = combo >> 1, d = combo & 1;
    int tt = d ? (Lc - 1 - t) : t;
    const __half* Ah = g_h + ((size_t)parity*4 + combo)*2048*192;
    __half* Ho       = g_h + ((size_t)(parity ^ 1)*4 + combo)*2048*192;
    float* Cst       = g_c + (size_t)combo*2048*192;
    const uint32_t* Bw = g_whhp2 + (size_t)(phase*4 + combo)*96*768;
    const float* XW  = g_xw + (size_t)combo*XW_S;
    __half* hs = g_hseq + (size_t)s*HS_S;
    int row0 = blockIdx.y*128, col0 = blockIdx.x*64;
    int tid = threadIdx.x;
    WARP_IDS
    int odd = qn & 1;
    float acc[2][4][4] = {};
    LOAD_AH128(0, Ah, Nseq-1, 0)
    LOAD_BH64(0, Bw, 0)
    cp_commit();
    #pragma unroll
    for (int c = 0; c < 6; ++c) {
        int cur = c & 1;
        if (c < 5) {
            LOAD_AH128(cur^1, Ah, Nseq-1, (c+1)*32)
            LOAD_BH64(cur^1, Bw, (c+1)*16)
            cp_commit();
            cp_wait1();
        } else cp_wait0();
        __syncthreads();
        MMA_H_N64(cur)
        __syncthreads();
    }
    #pragma unroll
    for (int mt = 0; mt < 2; ++mt) {
        int rlo = row0 + wm*32 + mt*16 + gp;
        int rhi = rlo + 8;
        int row = odd ? rhi : rlo;
        #pragma unroll
        for (int nt = 0; nt < 4; ++nt) {
            float sx0 = __shfl_xor_sync(0xffffffffu, acc[mt][nt][0], 1);
            float sx1 = __shfl_xor_sync(0xffffffffu, acc[mt][nt][1], 1);
            float sx2 = __shfl_xor_sync(0xffffffffu, acc[mt][nt][2], 1);
            float sx3 = __shfl_xor_sync(0xffffffffu, acc[mt][nt][3], 1);
            float gi, gf, gg, go;
            if (!odd) { gi = acc[mt][nt][0]; gf = acc[mt][nt][1]; gg = sx0; go = sx1; }
            else      { gi = sx2; gf = sx3; gg = acc[mt][nt][2]; go = acc[mt][nt][3]; }
            if (row < Nseq) {
                int ug = (col0 >> 2) + wn*8 + nt*2 + (qn >> 1);
                float4 xv = *(const float4*)&XW[((size_t)row*Lc + tt)*768 + ug*4];
                float I = gi + xv.x, F = gf + xv.y, G = gg + xv.z, O = go + xv.w;
                float cp = Cst[(size_t)row*192 + ug];
                float cn = sigf(F)*cp + sigf(I)*tanhf(G);
                float hn = sigf(O)*tanhf(cn);
                Cst[(size_t)row*192 + ug] = cn;
                __half hh = __float2half(hn);
                Ho[(size_t)row*192 + ug]  = hh;
                hs[((size_t)row*Lc + tt)*384 + d*192 + ug] = hh;
            }
        }
    }
}

// ---------------- convT1d gather-GEMM + bias + residual (fp16 mma, M128N64) ----------------
__global__ void __launch_bounds__(256, 2) convt_gemm(int phase, const float* __restrict__ Tb,
                                                     const float* __restrict__ x0, const float* __restrict__ x1)
{
    extern __shared__ uint32_t smemu[];
    uint32_t* sA = smemu;
    uint32_t* sB = smemu + 2*2560;
    int s = blockIdx.z;
    int Lc   = phase ? L1 : L0;
    int Qlen = phase ? 512 : 65;
    const __half* hs = g_hseq + (size_t)s*HS_S;
    const uint32_t* Bw = g_twt2 + (size_t)(phase*2 + s)*768*48;
    int row0 = blockIdx.y*128;
    int tid = threadIdx.x;
    WARP_IDS
    float acc[2][4][4] = {};

    // chunk = 32 halves of the 1536-dim (16 k2 rows)
    #define CONV_LOAD(buf, kcc) { \
        int ktap = (kcc) / 384; \
        int i0 = (kcc) - ktap*384; \
        _Pragma("unroll") for (int rep = 0; rep < 2; ++rep) { \
            int idx = tid + rep*256; \
            int rr = idx >> 2, seg = idx & 3; \
            int gr = row0 + rr; \
            int n = gr / Qlen, q = gr - n*Qlen; \
            int l = q - ktap; \
            bool val = (l >= 0 && l < Lc); \
            const __half* src = val ? &hs[((size_t)n*Lc + l)*384 + i0 + seg*8] : hs; \
            cp16z(&AH(buf,rr,seg*4), src, val); } \
        { \
            int k = tid >> 4, seg = tid & 15; \
            bool val = (seg*4 < 48); \
            const uint32_t* src = val ? &Bw[(size_t)(((kcc)>>1) + k)*48 + seg*4] : Bw; \
            cp16z(&BH64(buf,k,seg*4), src, val); } }

    CONV_LOAD(0, 0)
    cp_commit();
    for (int c = 0; c < 48; ++c) {
        int cur = c & 1;
        if (c < 47) {
            CONV_LOAD(cur^1, (c+1)*32)
            cp_commit();
            cp_wait1();
        } else cp_wait0();
        __syncthreads();
        MMA_H_N64(cur)
        __syncthreads();
    }
    #undef CONV_LOAD
    int g = phase*2 + s;
    #pragma unroll
    for (int mt = 0; mt < 2; ++mt) {
        int rbase = row0 + wm*32 + mt*16 + gp;
        #pragma unroll
        for (int nt = 0; nt < 4; ++nt) {
            int cb = wn*32 + nt*8 + 2*qn;
            #pragma unroll
            for (int half = 0; half < 2; ++half) {
                int row = rbase + half*8;
                int n = row / Qlen, q = row - n*Qlen;
                #pragma unroll
                for (int j = 0; j < 2; ++j) {
                    int c = cb + j;
                    if (c < 48) {
                        float v = acc[mt][nt][half*2 + j] + Tb[g*48 + c];
                        if (phase == 0) {
                            int b = n >> 9, tpos = n & 511;
                            size_t oi = ((size_t)(b*48 + c)*512 + tpos)*65 + q;
                            const float* res = s ? x1 : x0;
                            g_io[(size_t)s*TSZ + oi] = v + res[oi];
                        } else {
                            int b = n / 65, f = n - b*65;
                            size_t oi = ((size_t)(b*48 + c)*512 + q)*65 + f;
                            g_eo[(size_t)s*TSZ + oi] = v + g_io[(size_t)s*TSZ + oi];
                        }
                    }
                }
            }
        }
    }
}

// ---------------- q/k/v head projections + leaky + LN (K written transposed) ----------------
__global__ void __launch_bounds__(256) qkv_kernel(
    const float* __restrict__ AWqk, const float* __restrict__ Abqk, const float* __restrict__ Aaqk,
    const float* __restrict__ Agqk, const float* __restrict__ Abgqk,
    const float* __restrict__ AWv,  const float* __restrict__ Abv,  const float* __restrict__ Aav,
    const float* __restrict__ Agv,  const float* __restrict__ Abgv)
{
    int t = blockIdx.x, b = blockIdx.y, s = blockIdx.z, tid = threadIdx.x;
    int lane = tid & 31, warp = tid >> 5;
    __shared__ float zs[3120];
    __shared__ float buf[780];
    __shared__ float red[32];
    const float* z = g_eo + (size_t)s*TSZ;
    for (int i = tid; i < 3120; i += 256) {
        int c = i / 65, f = i - c*65;
        zs[i] = z[((size_t)(b*48 + c)*512 + t)*65 + f];
    }
    __syncthreads();
    for (int grp = 0; grp < 12; ++grp) {
        int tensor = grp >> 2, h = grp & 3;
        int nvals;
        const float *W, *bb, *gam, *bet;
        float alpha;
        if (tensor < 2) {
            nvals = 520;
            int hh = (s*2 + tensor)*4 + h;
            W = AWqk + (size_t)hh*8*48; bb = Abqk + hh*8; alpha = Aaqk[hh];
            gam = Agqk + (size_t)hh*8*65; bet = Abgqk + (size_t)hh*8*65;
        } else {
            nvals = 780;
            int hh = s*4 + h;
            W = AWv + (size_t)hh*12*48; bb = Abv + hh*12; alpha = Aav[hh];
            gam = Agv + (size_t)hh*12*65; bet = Abgv + (size_t)hh*12*65;
        }
        float ls = 0.f, lq = 0.f;
        for (int idx = tid; idx < nvals; idx += 256) {
            int e = idx / 65, f = idx - e*65;
            float a = bb[e];
            const float* wr = W + e*48;
            #pragma unroll
            for (int c = 0; c < 48; ++c) a += zs[c*65 + f]*wr[c];
            a = a >= 0.f ? a : alpha*a;
            buf[idx] = a; ls += a; lq += a*a;
        }
        #pragma unroll
        for (int o = 16; o; o >>= 1) {
            ls += __shfl_xor_sync(0xffffffffu, ls, o);
            lq += __shfl_xor_sync(0xffffffffu, lq, o);
        }
        if (lane == 0) { red[warp] = ls; red[8 + warp] = lq; }
        __syncthreads();
        if (tid == 0) {
            float a = 0.f, c = 0.f;
            #pragma unroll
            for (int i = 0; i < 8; ++i) { a += red[i]; c += red[8 + i]; }
            red[16] = a; red[17] = c;
        }
        __syncthreads();
        float mu = red[16] / nvals;
        float inv = rsqrtf(red[17] / nvals - mu*mu + EPSLN);
        int bz = s*16 + b*4 + h;
        if (tensor == 0) {
            float* outp = g_q + ((size_t)bz*512 + t)*EK2;
            for (int idx = tid; idx < nvals; idx += 256)
                outp[idx] = (buf[idx] - mu)*inv*gam[idx] + bet[idx];
            if (tid < EK2 - 520) outp[520 + tid] = 0.f;
        } else if (tensor == 1) {
            float* outp = g_k + (size_t)bz*EK2*512;
            for (int idx = tid; idx < nvals; idx += 256)
                outp[(size_t)idx*512 + t] = (buf[idx] - mu)*inv*gam[idx] + bet[idx];
            if (tid < EK2 - 520) outp[(size_t)(520 + tid)*512 + t] = 0.f;
        } else {
            float* outp = g_v + ((size_t)bz*512 + t)*780;
            for (int idx = tid; idx < nvals; idx += 256)
                outp[idx] = (buf[idx] - mu)*inv*gam[idx] + bet[idx];
        }
        __syncthreads();
    }
}

// ---------------- QK^T (scaled, tf32 XL) ----------------
__global__ void __launch_bounds__(256, 2) qk_gemm()
{
    extern __shared__ uint32_t smemu[];
    uint32_t* sA = smemu;
    uint32_t* sB = smemu + 2*4608;
    int bz = blockIdx.z;
    const float* Q  = g_q + (size_t)bz*512*EK2;
    const float* Kt = g_k + (size_t)bz*EK2*512;
    float* Co = g_attn + (size_t)bz*512*512;
    int row0 = blockIdx.y*128, col0 = blockIdx.x*128;
    int tid = threadIdx.x;
    WARP_IDS
    float acc[2][8][4] = {};
    LOAD_A128F(0, Q, EK2, 511, 0)
    LOAD_BXLF(0, Kt, 512, 0)
    cp_commit();
    for (int c = 0; c < 17; ++c) {
        int cur = c & 1;
        if (c < 16) {
            LOAD_A128F(cur^1, Q, EK2, 511, (c+1)*32)
            LOAD_BXLF(cur^1, Kt, 512, (c+1)*32)
            cp_commit();
            cp_wait1();
        } else cp_wait0();
        __syncthreads();
        MMA_XLF(cur)
        __syncthreads();
    }
    float rs = rsqrtf(520.f);
    #pragma unroll
    for (int mt = 0; mt < 2; ++mt) {
        int r = row0 + wm*32 + mt*16 + gp;
        #pragma unroll
        for (int nt = 0; nt < 8; ++nt) {
            int cb = col0 + wn*64 + nt*8 + 2*qn;
            *(float2*)&Co[(size_t)r*512 + cb]     = make_float2(acc[mt][nt][0]*rs, acc[mt][nt][1]*rs);
            *(float2*)&Co[(size_t)(r+8)*512 + cb] = make_float2(acc[mt][nt][2]*rs, acc[mt][nt][3]*rs);
        }
    }
}

// ---------------- row softmax ----------------
__global__ void __launch_bounds__(256) softmax_rows()
{
    int row = blockIdx.x, bz = blockIdx.y, tid = threadIdx.x;
    float* p = g_attn + (size_t)bz*512*512 + (size_t)row*512;
    __shared__ float sm[512];
    __shared__ float red[256];
    sm[tid] = p[tid]; sm[tid + 256] = p[tid + 256];
    red[tid] = fmaxf(sm[tid], sm[tid + 256]);
    __syncthreads();
    for (int st = 128; st > 0; st >>= 1) {
        if (tid < st) red[tid] = fmaxf(red[tid], red[tid + st]);
        __syncthreads();
    }
    float mx = red[0];
    __syncthreads();
    float e0 = expf(sm[tid] - mx), e1 = expf(sm[tid + 256] - mx);
    red[tid] = e0 + e1;
    __syncthreads();
    for (int st = 128; st > 0; st >>= 1) {
        if (tid < st) red[tid] += red[tid + st];
        __syncthreads();
    }
    float invs = 1.f / red[0];
    p[tid] = e0*invs; p[tid + 256] = e1*invs;
}

// ---------------- P @ V (tf32 XL) ----------------
__global__ void __launch_bounds__(256, 2) pv_gemm()
{
    extern __shared__ uint32_t smemu[];
    uint32_t* sA = smemu;
    uint32_t* sB = smemu + 2*4608;
    int bz = blockIdx.z;
    const float* A  = g_attn + (size_t)bz*512*512;
    const float* Bv = g_v + (size_t)bz*512*780;
    float* Co = g_av + (size_t)bz*512*780;
    int row0 = blockIdx.y*128, col0 = blockIdx.x*128;
    int tid = threadIdx.x;
    WARP_IDS
    float acc[2][8][4] = {};
    LOAD_A128F(0, A, 512, 511, 0)
    LOAD_BXLF_G(0, Bv, 780, 0, 780)
    cp_commit();
    for (int c = 0; c < 16; ++c) {
        int cur = c & 1;
        if (c < 15) {
            LOAD_A128F(cur^1, A, 512, 511, (c+1)*32)
            LOAD_BXLF_G(cur^1, Bv, 780, (c+1)*32, 780)
            cp_commit();
            cp_wait1();
        } else cp_wait0();
        __syncthreads();
        MMA_XLF(cur)
        __syncthreads();
    }
    #pragma unroll
    for (int mt = 0; mt < 2; ++mt) {
        int r = row0 + wm*32 + mt*16 + gp;
        #pragma unroll
        for (int nt = 0; nt < 8; ++nt) {
            int cb = col0 + wn*64 + nt*8 + 2*qn;
            #pragma unroll
            for (int j = 0; j < 2; ++j) {
                int col = cb + j;
                if (col < 780) {
                    Co[(size_t)r*780 + col]     = acc[mt][nt][j];
                    Co[(size_t)(r+8)*780 + col] = acc[mt][nt][2 + j];
                }
            }
        }
    }
}

// ---------------- output projection + leaky + LN + residual ----------------
__global__ void __launch_bounds__(256) outproj_kernel(
    const float* __restrict__ AWp, const float* __restrict__ Abp, const float* __restrict__ Aap,
    const float* __restrict__ Agp, const float* __restrict__ Abgp, float* __restrict__ dout)
{
    int t = blockIdx.x, b = blockIdx.y, s = blockIdx.z, tid = threadIdx.x;
    int lane = tid & 31, warp = tid >> 5;
    __shared__ float os[3120];
    __shared__ float buf[3120];
    __shared__ float red[32];
    for (int i = tid; i < 3120; i += 256) {
        int c = i / 65, f = i - c*65;
        int h = c / 12, dv = c - h*12;
        os[i] = g_av[((size_t)((s*16 + b*4 + h)*512) + t)*780 + dv*65 + f];
    }
    __syncthreads();
    float alpha = Aap[s];
    float ls = 0.f, lq = 0.f;
    for (int idx = tid; idx < 3120; idx += 256) {
        int o = idx / 65, f = idx - o*65;
        float a = Abp[s*48 + o];
        const float* wr = AWp + (size_t)(s*48 + o)*48;
        #pragma unroll
        for (int c = 0; c < 48; ++c) a += os[c*65 + f]*wr[c];
        a = a >= 0.f ? a : alpha*a;
        buf[idx] = a; ls += a; lq += a*a;
    }
    #pragma unroll
    for (int o = 16; o; o >>= 1) {
        ls += __shfl_xor_sync(0xffffffffu, ls, o);
        lq += __shfl_xor_sync(0xffffffffu, lq, o);
    }
    if (lane == 0) { red[warp] = ls; red[8 + warp] = lq; }
    __syncthreads();
    if (tid == 0) {
        float a = 0.f, c = 0.f;
        #pragma unroll
        for (int i = 0; i < 8; ++i) { a += red[i]; c += red[8 + i]; }
        red[16] = a; red[17] = c;
    }
    __syncthreads();
    float mu = red[16] / 3120.f;
    float inv = rsqrtf(red[17] / 3120.f - mu*mu + EPSLN);
    for (int idx = tid; idx < 3120; idx += 256) {
        int o = idx / 65, f = idx - o*65;
        float v = (buf[idx] - mu)*inv*Agp[(s*48 + o)*65 + f] + Abgp[(s*48 + o)*65 + f]
                + g_eo[(size_t)s*TSZ + ((size_t)(b*48 + o)*512 + t)*65 + f];
        dout[(((size_t)(s*4 + b)*48 + o)*512 + t)*65 + f] = v;
    }
}

// ---------------- host launch ----------------
extern "C" void kernel_launch(void* const* d_in, const int* in_sizes, int n_in,
                              void* d_out, int out_size)
{
    const float* x     = (const float*)d_in[0];
    const float* c2    = (const float*)d_in[1];
    const float* ng    = (const float*)d_in[2];
    const float* nb    = (const float*)d_in[3];
    const float* LWih  = (const float*)d_in[4];
    const float* LWhh  = (const float*)d_in[5];
    const float* Lb    = (const float*)d_in[6];
    const float* TW    = (const float*)d_in[7];
    const float* Tb    = (const float*)d_in[8];
    const float* AWqk  = (const float*)d_in[9];
    const float* Abqk  = (const float*)d_in[10];
    const float* Aaqk  = (const float*)d_in[11];
    const float* Agqk  = (const float*)d_in[12];
    const float* Abgqk = (const float*)d_in[13];
    const float* AWv   = (const float*)d_in[14];
    const float* Abv   = (const float*)d_in[15];
    const float* Aav   = (const float*)d_in[16];
    const float* Agv   = (const float*)d_in[17];
    const float* Abgv  = (const float*)d_in[18];
    const float* AWp   = (const float*)d_in[19];
    const float* Abp   = (const float*)d_in[20];
    const float* Aap   = (const float*)d_in[21];
    const float* Agp   = (const float*)d_in[22];
    const float* Abgp  = (const float*)d_in[23];
    float* out = (float*)d_out;

    cudaFuncSetAttribute(xw_gemm,    cudaFuncAttributeMaxDynamicSharedMemorySize, SMEM_H128);
    cudaFuncSetAttribute(lstm_step,  cudaFuncAttributeMaxDynamicSharedMemorySize, SMEM_H64);
    cudaFuncSetAttribute(convt_gemm, cudaFuncAttributeMaxDynamicSharedMemorySize, SMEM_H64);
    cudaFuncSetAttribute(qk_gemm,    cudaFuncAttributeMaxDynamicSharedMemorySize, SMEM_XL);
    cudaFuncSetAttribute(pv_gemm,    cudaFuncAttributeMaxDynamicSharedMemorySize, SMEM_XL);

    pack_weights<<<512, 256>>>(LWih, LWhh, Lb, TW);

    // ---- phase 0: intra ----
    zero_state<<<512, 256>>>();
    ln_unfold_intra<<<dim3(512, 4, 2), 256>>>(x, c2, ng, nb);
    xw_gemm<<<dim3(6, (ROWS0 + 127)/128, 4), 256, SMEM_H128>>>(0, ROWS0);
    for (int t = 0; t < L0; ++t)
        lstm_step<<<dim3(12, 16, 4), 256, SMEM_H64>>>(t, 0, t & 1, N0, L0);
    convt_gemm<<<dim3(1, CONV_ROWS/128, 2), 256, SMEM_H64>>>(0, Tb, x, c2);

    // ---- phase 1: inter ----
    zero_state<<<512, 256>>>();
    ln_unfold_inter<<<dim3(512, 4, 2), 256>>>(ng, nb);
    xw_gemm<<<dim3(6, (ROWS1 + 127)/128, 4), 256, SMEM_H128>>>(1, ROWS1);
    for (int t = 0; t < L1; ++t)
        lstm_step<<<dim3(12, (N1 + 127)/128, 4), 256, SMEM_H64>>>(t, 1, t & 1, N1, L1);
    convt_gemm<<<dim3(1, CONV_ROWS/128, 2), 256, SMEM_H64>>>(1, Tb, x, c2);

    // ---- attention ----
    qkv_kernel<<<dim3(512, 4, 2), 256>>>(AWqk, Abqk, Aaqk, Agqk, Abgqk,
                                         AWv, Abv, Aav, Agv, Abgv);
    qk_gemm<<<dim3(4, 4, 32), 256, SMEM_XL>>>();
    softmax_rows<<<dim3(512, 32), 256>>>();
    pv_gemm<<<dim3(7, 4, 32), 256, SMEM_XL>>>();
    outproj_kernel<<<dim3(512, 4, 2), 256>>>(AWp, Abp, Aap, Agp, Abgp, out);
}

// round 16
// speedup vs baseline: 1.5249x; 1.1441x over previous
#include <cuda_runtime.h>
#include <cuda_fp16.h>
#include <math.h>
#include <stdint.h>

// ---------------- constants ----------------
#define Bb 4
#define Cc 48
#define Tt 512
#define Ff 65
#define L0 62
#define L1 509
#define N0 2048
#define N1 260
#define ROWS0 126976
#define ROWS1 132340
#define ROWSMAX 132340
#define CONV_ROWS 133120
#define XU_S  ((size_t)ROWSMAX*192)
#define XW_S  ((size_t)ROWSMAX*768)
#define HS_S  ((size_t)ROWSMAX*384)
#define TSZ   (Bb*Cc*Tt*Ff)
#define EK2   544
#define EPSLN 1e-5f

#define SMEM_XL   ((2*128*36 + 2*32*136)*4)   // 71680  (qk/pv tf32)
#define SMEM_H128 ((2*128*20 + 2*16*136)*4)   // 37888  (xw fp16)
#define SMEM_H64  ((2*128*20 + 2*16*72)*4)    // 29696  (convt fp16)
#define SMEM_SEQ  ((16*100 + 2*16*776)*4)     // 105728 (persistent per-row lstm)

// ---------------- device scratch ----------------
__device__ __half g_xu[2*XU_S];
__device__ float  g_xw[4*XW_S];
__device__ __half g_hseq[2*HS_S];
__device__ uint32_t g_wihp2[8*96*768];   // [w][j2][col]  packed (2j2,2j2+1)
__device__ uint32_t g_whhp2[8*96*768];
__device__ float  g_bp[8*768];
__device__ uint32_t g_twt2[4*768*48];    // [g][k2][o]
__device__ float  g_io[2*TSZ];
__device__ float  g_eo[2*TSZ];
__device__ float  g_q[(size_t)2*16*512*EK2];
__device__ float  g_k[(size_t)2*16*EK2*512];   // [bz][k][t]
__device__ float  g_v[2*16*512*780];
__device__ float  g_attn[(size_t)2*16*512*512];
__device__ float  g_av[2*16*512*780];

__device__ __forceinline__ float sigf(float x){ return 1.f/(1.f+expf(-x)); }

__device__ __forceinline__ void mma_tf32(float* c, uint32_t a0, uint32_t a1,
                                         uint32_t a2, uint32_t a3,
                                         uint32_t b0, uint32_t b1){
    asm volatile("mma.sync.aligned.m16n8k8.row.col.f32.tf32.tf32.f32 "
        "{%0,%1,%2,%3}, {%4,%5,%6,%7}, {%8,%9}, {%0,%1,%2,%3};"
        : "+f"(c[0]), "+f"(c[1]), "+f"(c[2]), "+f"(c[3])
        : "r"(a0), "r"(a1), "r"(a2), "r"(a3), "r"(b0), "r"(b1));
}

__device__ __forceinline__ void mma_f16(float* c, uint32_t a0, uint32_t a1,
                                        uint32_t a2, uint32_t a3,
                                        uint32_t b0, uint32_t b1){
    asm volatile("mma.sync.aligned.m16n8k16.row.col.f32.f16.f16.f32 "
        "{%0,%1,%2,%3}, {%4,%5,%6,%7}, {%8,%9}, {%0,%1,%2,%3};"
        : "+f"(c[0]), "+f"(c[1]), "+f"(c[2]), "+f"(c[3])
        : "r"(a0), "r"(a1), "r"(a2), "r"(a3), "r"(b0), "r"(b1));
}

// cp.async helpers
__device__ __forceinline__ void cp16(void* smem, const void* gmem){
    uint32_t s = (uint32_t)__cvta_generic_to_shared(smem);
    asm volatile("cp.async.ca.shared.global [%0], [%1], 16;\n" :: "r"(s), "l"(gmem) : "memory");
}
__device__ __forceinline__ void cp16z(void* smem, const void* gmem, bool valid){
    uint32_t s = (uint32_t)__cvta_generic_to_shared(smem);
    int sz = valid ? 16 : 0;
    asm volatile("cp.async.ca.shared.global [%0], [%1], 16, %2;\n" :: "r"(s), "l"(gmem), "r"(sz) : "memory");
}
__device__ __forceinline__ void cp_commit(){ asm volatile("cp.async.commit_group;\n" ::: "memory"); }
__device__ __forceinline__ void cp_wait0(){ asm volatile("cp.async.wait_group 0;\n" ::: "memory"); }
__device__ __forceinline__ void cp_wait1(){ asm volatile("cp.async.wait_group 1;\n" ::: "memory"); }

// ------------- shared tile indexing -------------
#define BXL(buf,k,n)  sB[(buf)*4352 + (k)*136 + (n)]
#define AH(buf,m,k2)    sA[(buf)*2560 + (m)*20 + (k2)]
#define BH64(buf,k2,n)  sB[(buf)*1152 + (k2)*72 + (n)]
#define BH128(buf,k2,n) sB[(buf)*2176 + (k2)*136 + (n)]

#define WARP_IDS \
    int lane = tid & 31, warp = tid >> 5; \
    int wm = warp >> 1, wn = warp & 1;    \
    int gp = lane >> 2, qn = lane & 3;

#define LOAD_AH128(buf, Aptr, rowClamp, kcc) { \
    _Pragma("unroll") for (int rep = 0; rep < 2; ++rep) { \
        int idx = tid + rep*256; \
        int row = idx >> 2, seg = idx & 3; \
        int gr = row0 + row; if (gr > (rowClamp)) gr = (rowClamp); \
        cp16(&AH(buf,row,seg*4), &(Aptr)[(size_t)gr*192 + (kcc) + seg*8]); } }

#define LOAD_BH64(buf, Bptr, kcc2) { \
    int k = tid >> 4, seg = tid & 15; \
    cp16(&BH64(buf,k,seg*4), &(Bptr)[(size_t)((kcc2)+k)*768 + col0 + seg*4]); }

#define LOAD_BH128(buf, Bptr, kcc2) { \
    _Pragma("unroll") for (int rep = 0; rep < 2; ++rep) { \
        int idx = tid + rep*256; \
        int k = idx >> 5, seg = idx & 31; \
        cp16(&BH128(buf,k,seg*4), &(Bptr)[(size_t)((kcc2)+k)*768 + col0 + seg*4]); } }

#define MMA_H_XL(buf) \
    _Pragma("unroll") for (int ks = 0; ks < 2; ++ks) { \
        int kq = ks*8 + qn; \
        int am0 = wm*32 + gp; \
        uint32_t a00=AH(buf,am0,kq),    a01=AH(buf,am0+8,kq); \
        uint32_t a02=AH(buf,am0,kq+4),  a03=AH(buf,am0+8,kq+4); \
        uint32_t a10=AH(buf,am0+16,kq),   a11=AH(buf,am0+24,kq); \
        uint32_t a12=AH(buf,am0+16,kq+4), a13=AH(buf,am0+24,kq+4); \
        int bn = wn*64 + gp; \
        _Pragma("unroll") for (int nt = 0; nt < 8; ++nt) { \
            uint32_t b0 = BH128(buf,kq,bn+nt*8), b1 = BH128(buf,kq+4,bn+nt*8); \
            mma_f16(acc[0][nt], a00,a01,a02,a03, b0,b1); \
            mma_f16(acc[1][nt], a10,a11,a12,a13, b0,b1); } }

#define MMA_H_N64(buf) \
    _Pragma("unroll") for (int ks = 0; ks < 2; ++ks) { \
        int kq = ks*8 + qn; \
        int am0 = wm*32 + gp; \
        uint32_t a00=AH(buf,am0,kq),    a01=AH(buf,am0+8,kq); \
        uint32_t a02=AH(buf,am0,kq+4),  a03=AH(buf,am0+8,kq+4); \
        uint32_t a10=AH(buf,am0+16,kq),   a11=AH(buf,am0+24,kq); \
        uint32_t a12=AH(buf,am0+16,kq+4), a13=AH(buf,am0+24,kq+4); \
        int bn = wn*32 + gp; \
        _Pragma("unroll") for (int nt = 0; nt < 4; ++nt) { \
            uint32_t b0 = BH64(buf,kq,bn+nt*8), b1 = BH64(buf,kq+4,bn+nt*8); \
            mma_f16(acc[0][nt], a00,a01,a02,a03, b0,b1); \
            mma_f16(acc[1][nt], a10,a11,a12,a13, b0,b1); } }

// tf32 staging for qk/pv
#define LOAD_A128F(buf, Aptr, lda, rowClamp, kcc) { \
    _Pragma("unroll") for (int rep = 0; rep < 4; ++rep) { \
        int idx = tid + rep*256; \
        int row = idx >> 3, seg = idx & 7; \
        int gr = row0 + row; if (gr > (rowClamp)) gr = (rowClamp); \
        cp16(&sA[(buf)*4608 + row*36 + seg*4], &(Aptr)[(size_t)gr*(lda) + (kcc) + seg*4]); } }

#define LOAD_BXLF(buf, Bptr, ldb, kcc) { \
    _Pragma("unroll") for (int rep = 0; rep < 4; ++rep) { \
        int idx = tid + rep*256; \
        int k = idx >> 5, seg = idx & 31; \
        cp16(&BXL(buf,k,seg*4), &(Bptr)[(size_t)((kcc) + k)*(ldb) + col0 + seg*4]); } }

#define LOAD_BXLF_G(buf, Bptr, ldb, kcc, Ncols) { \
    _Pragma("unroll") for (int rep = 0; rep < 4; ++rep) { \
        int idx = tid + rep*256; \
        int k = idx >> 5, seg = idx & 31; \
        int cc = col0 + seg*4; \
        bool val = (cc < (Ncols)); \
        const float* src = val ? &(Bptr)[(size_t)((kcc) + k)*(ldb) + cc] : (const float*)(Bptr); \
        cp16z(&BXL(buf,k,seg*4), src, val); } }

#define ASIF(buf,m,k) sA[(buf)*4608 + (m)*36 + (k)]
#define MMA_XLF(buf) \
    _Pragma("unroll") for (int k8 = 0; k8 < 4; ++k8) { \
        int kb = k8*8 + qn; \
        int am0 = wm*32 + gp; \
        uint32_t a00=ASIF(buf,am0,kb),    a01=ASIF(buf,am0+8,kb); \
        uint32_t a02=ASIF(buf,am0,kb+4),  a03=ASIF(buf,am0+8,kb+4); \
        uint32_t a10=ASIF(buf,am0+16,kb),   a11=ASIF(buf,am0+24,kb); \
        uint32_t a12=ASIF(buf,am0+16,kb+4), a13=ASIF(buf,am0+24,kb+4); \
        int bn = wn*64 + gp; \
        _Pragma("unroll") for (int nt = 0; nt < 8; ++nt) { \
            uint32_t b0 = BXL(buf,kb,bn+nt*8), b1 = BXL(buf,kb+4,bn+nt*8); \
            mma_tf32(acc[0][nt], a00,a01,a02,a03, b0,b1); \
            mma_tf32(acc[1][nt], a10,a11,a12,a13, b0,b1); } }

// ---------------- weight packing (fp16 pair-packed along k) ----------------
__global__ void pack_weights(const float* __restrict__ LWih, const float* __restrict__ LWhh,
                             const float* __restrict__ Lb,   const float* __restrict__ TW)
{
    int stride = gridDim.x * blockDim.x;
    int t0 = blockIdx.x * blockDim.x + threadIdx.x;
    for (int idx = t0; idx < 8*96*768; idx += stride) {
        int w = idx / (96*768);
        int r = idx - w*(96*768);
        int j2 = r / 768, col = r - j2*768;
        int u = col >> 2, gt = col & 3;
        int g = (w>>2)*2 + ((w>>1)&1);
        int d = w & 1;
        size_t src = ((size_t)(g*2+d)*768 + gt*192 + u);
        __half2 hi = __floats2half2_rn(LWih[src*192 + 2*j2], LWih[src*192 + 2*j2 + 1]);
        __half2 hh = __floats2half2_rn(LWhh[src*192 + 2*j2], LWhh[src*192 + 2*j2 + 1]);
        g_wihp2[idx] = *(uint32_t*)&hi;
        g_whhp2[idx] = *(uint32_t*)&hh;
    }
    for (int idx = t0; idx < 8*768; idx += stride) {
        int w = idx / 768, col = idx - w*768;
        int u = col >> 2, gt = col & 3;
        int g = (w>>2)*2 + ((w>>1)&1);
        int d = w & 1;
        g_bp[idx] = Lb[(g*2+d)*768 + gt*192 + u];
    }
    for (int idx = t0; idx < 4*768*48; idx += stride) {
        int g = idx / (768*48);
        int r = idx - g*(768*48);
        int k2 = r / 48, o = r - k2*48;
        int kk = 2*k2;
        int k = kk / 384, i = kk - k*384;
        __half2 tv = __floats2half2_rn(
            TW[(((size_t)g*384 + i  )*48 + o)*4 + k],
            TW[(((size_t)g*384 + i+1)*48 + o)*4 + k]);
        g_twt2[idx] = *(uint32_t*)&tv;
    }
}

// ---------------- LN over C + unfold, intra ----------------
__global__ void ln_unfold_intra(const float* __restrict__ x0, const float* __restrict__ x1,
                                const float* __restrict__ ng, const float* __restrict__ nb)
{
    int t = blockIdx.x, b = blockIdx.y, s = blockIdx.z;
    const float* src = s ? x1 : x0;
    __shared__ float zs[48*65];
    __shared__ float mu[65], inv[65];
    int tid = threadIdx.x;
    for (int i = tid; i < 48*65; i += 256) {
        int c = i / 65, f = i - c*65;
        zs[i] = src[((size_t)(b*48 + c)*512 + t)*65 + f];
    }
    __syncthreads();
    if (tid < 65) {
        float s1 = 0.f, s2 = 0.f;
        #pragma unroll
        for (int c = 0; c < 48; ++c) { float v = zs[c*65 + tid]; s1 += v; s2 += v*v; }
        float m = s1 * (1.f/48.f);
        mu[tid] = m;
        inv[tid] = rsqrtf(s2*(1.f/48.f) - m*m + EPSLN);
    }
    __syncthreads();
    size_t n = (size_t)b*512 + t;
    __half* outp = g_xu + (size_t)s*XU_S + n*(size_t)L0*192;
    for (int i = tid; i < 48*L0*4; i += 256) {
        int c = i / (L0*4);
        int r = i - c*(L0*4);
        int l = r >> 2, k = r & 3;
        int q = l + k;
        float v = (zs[c*65 + q] - mu[q]) * inv[q] * ng[s*48 + c] + nb[s*48 + c];
        outp[(size_t)l*192 + c*4 + k] = __float2half(v);
    }
}

// ---------------- LN over C + unfold, inter ----------------
__global__ void ln_unfold_inter(const float* __restrict__ ng, const float* __restrict__ nb)
{
    int t = blockIdx.x, b = blockIdx.y, s = blockIdx.z;
    const float* src = g_io + (size_t)s*TSZ;
    __shared__ float zs[48*65];
    __shared__ float mu[65], inv[65];
    int tid = threadIdx.x;
    for (int i = tid; i < 48*65; i += 256) {
        int c = i / 65, f = i - c*65;
        zs[i] = src[((size_t)(b*48 + c)*512 + t)*65 + f];
    }
    __syncthreads();
    if (tid < 65) {
        float s1 = 0.f, s2 = 0.f;
        #pragma unroll
        for (int c = 0; c < 48; ++c) { float v = zs[c*65 + tid]; s1 += v; s2 += v*v; }
        float m = s1 * (1.f/48.f);
        mu[tid] = m;
        inv[tid] = rsqrtf(s2*(1.f/48.f) - m*m + EPSLN);
    }
    __syncthreads();
    int gi = 2 + s;
    for (int i = tid; i < 48*65; i += 256) {
        int c = i / 65, f = i - c*65;
        float v = (zs[i] - mu[f]) * inv[f] * ng[gi*48 + c] + nb[gi*48 + c];
        size_t n = (size_t)b*65 + f;
        __half* outp = g_xu + (size_t)s*XU_S + n*(size_t)L1*192;
        __half hv = __float2half(v);
        #pragma unroll
        for (int k = 0; k < 4; ++k) {
            int l = t - k;
            if (l >= 0 && l < L1) outp[(size_t)l*192 + c*4 + k] = hv;
        }
    }
}

// ---------------- xw = xu @ Wih^T + b  (fp16 mma, 128x128) ----------------
__global__ void __launch_bounds__(256, 2) xw_gemm(int phase, int M)
{
    extern __shared__ uint32_t smemu[];
    uint32_t* sA = smemu;              // [2][128][20]
    uint32_t* sB = smemu + 2*2560;     // [2][16][136]
    int combo = blockIdx.z;
    int s = combo >> 1;
    const __half* A      = g_xu + (size_t)s*XU_S;
    const uint32_t* Bw   = g_wihp2 + (size_t)(phase*4 + combo)*96*768;
    const float* bias    = g_bp + (size_t)(phase*4 + combo)*768;
    float* Co = g_xw + (size_t)combo*XW_S;
    int row0 = blockIdx.y*128, col0 = blockIdx.x*128;
    int tid = threadIdx.x;
    WARP_IDS
    float acc[2][8][4] = {};
    LOAD_AH128(0, A, M-1, 0)
    LOAD_BH128(0, Bw, 0)
    cp_commit();
    #pragma unroll
    for (int c = 0; c < 6; ++c) {
        int cur = c & 1;
        if (c < 5) {
            LOAD_AH128(cur^1, A, M-1, (c+1)*32)
            LOAD_BH128(cur^1, Bw, (c+1)*16)
            cp_commit();
            cp_wait1();
        } else cp_wait0();
        __syncthreads();
        MMA_H_XL(cur)
        __syncthreads();
    }
    #pragma unroll
    for (int mt = 0; mt < 2; ++mt) {
        int r = row0 + wm*32 + mt*16 + gp;
        #pragma unroll
        for (int nt = 0; nt < 8; ++nt) {
            int cb = col0 + wn*64 + nt*8 + 2*qn;
            float b0v = bias[cb], b1v = bias[cb+1];
            if (r < M)
                *(float2*)&Co[(size_t)r*768 + cb] = make_float2(acc[mt][nt][0]+b0v, acc[mt][nt][1]+b1v);
            if (r + 8 < M)
                *(float2*)&Co[(size_t)(r+8)*768 + cb] = make_float2(acc[mt][nt][2]+b0v, acc[mt][nt][3]+b1v);
        }
    }
}

// ---------------- persistent per-row LSTM: block owns 16 rows x ALL 768 cols x all steps ----------------
// No grid sync needed: the recurrence is row-local. Whh streamed from L2 each step (double-buffered).
__global__ void __launch_bounds__(256, 1) lstm_seq(int phase, int Nseq, int Lc)
{
    extern __shared__ uint32_t smemu[];
    uint32_t* hsm = smemu;            // [16][100]  (h as half2 words, pitch 100)
    uint32_t* Wsb = smemu + 1600;     // [2][16][776]
    __half*  hsm_h = (__half*)hsm;    // pitch 200 halves

    int combo = blockIdx.y;
    int s = combo >> 1, d = combo & 1;
    int row0 = blockIdx.x*16;
    int tid = threadIdx.x;
    int lane = tid & 31, w = tid >> 5;
    int gp = lane >> 2, qn = lane & 3;
    int odd = qn & 1;

    const uint32_t* Bw = g_whhp2 + (size_t)(phase*4 + combo)*96*768;
    const float* XW = g_xw + (size_t)combo*XW_S;
    __half* hs = g_hseq + (size_t)s*HS_S;

    for (int i = tid; i < 1600; i += 256) hsm[i] = 0;
    float creg[12];
    #pragma unroll
    for (int i = 0; i < 12; ++i) creg[i] = 0.f;

    int lrow = odd ? gp + 8 : gp;
    int grow = row0 + lrow;
    bool valid = grow < Nseq;
    int growC = valid ? grow : 0;

    #define SEQ_LOADB(buf, kc2base) { \
        _Pragma("unroll") for (int rep = 0; rep < 12; ++rep) { \
            int idx = tid + rep*256; \
            int k = idx / 192, seg = idx - k*192; \
            cp16(&Wsb[(buf)*12416 + k*776 + seg*4], &Bw[(size_t)((kc2base)+k)*768 + seg*4]); } }

    SEQ_LOADB(0, 0)
    cp_commit();
    SEQ_LOADB(1, 16)
    cp_commit();
    __syncthreads();   // hsm zeros visible

    for (int t = 0; t < Lc; ++t) {
        int tt = d ? (Lc - 1 - t) : t;
        float acc[12][4] = {};
        #pragma unroll
        for (int c6 = 0; c6 < 6; ++c6) {
            int buf = c6 & 1;
            cp_wait1();
            __syncthreads();
            #pragma unroll
            for (int ks = 0; ks < 2; ++ks) {
                int kq = ks*8 + qn;
                int kg = c6*16;
                uint32_t a0 = hsm[gp*100 + kg + kq];
                uint32_t a1 = hsm[(gp+8)*100 + kg + kq];
                uint32_t a2 = hsm[gp*100 + kg + kq + 4];
                uint32_t a3 = hsm[(gp+8)*100 + kg + kq + 4];
                const uint32_t* B0 = &Wsb[buf*12416 + kq*776];
                const uint32_t* B1 = &Wsb[buf*12416 + (kq+4)*776];
                int bn = w*96 + gp;
                #pragma unroll
                for (int nt = 0; nt < 12; ++nt)
                    mma_f16(acc[nt], a0, a1, a2, a3, B0[bn + nt*8], B1[bn + nt*8]);
            }
            __syncthreads();   // buffer consumed
            SEQ_LOADB(buf, (((c6 + 2) % 6))*16)   // same B every step: uniform refill
            cp_commit();
        }
        // epilogue: each thread owns 12 (row,unit) cells
        const float* xwr = &XW[((size_t)growC*Lc + tt)*768];
        #pragma unroll
        for (int nt = 0; nt < 12; ++nt) {
            float sx0 = __shfl_xor_sync(0xffffffffu, acc[nt][0], 1);
            float sx1 = __shfl_xor_sync(0xffffffffu, acc[nt][1], 1);
            float sx2 = __shfl_xor_sync(0xffffffffu, acc[nt][2], 1);
            float sx3 = __shfl_xor_sync(0xffffffffu, acc[nt][3], 1);
            float gi, gf, gg, go;
            if (!odd) { gi = acc[nt][0]; gf = acc[nt][1]; gg = sx0; go = sx1; }
            else      { gi = sx2; gf = sx3; gg = acc[nt][2]; go = acc[nt][3]; }
            int ug = w*24 + nt*2 + (qn >> 1);
            float4 xv = *(const float4*)&xwr[ug*4];
            float I = gi + xv.x, F = gf + xv.y, G = gg + xv.z, O = go + xv.w;
            float cn = sigf(F)*creg[nt] + sigf(I)*tanhf(G);
            float hn = sigf(O)*tanhf(cn);
            creg[nt] = cn;
            if (valid) {
                __half hh = __float2half(hn);
                hsm_h[lrow*200 + ug] = hh;
                hs[((size_t)grow*Lc + tt)*384 + d*192 + ug] = hh;
            }
        }
        __syncthreads();   // h writes visible before next step's A reads
    }
    cp_wait0();
    #undef SEQ_LOADB
}

// ---------------- convT1d gather-GEMM + bias + residual (fp16 mma, M128N64) ----------------
__global__ void __launch_bounds__(256, 2) convt_gemm(int phase, const float* __restrict__ Tb,
                                                     const float* __restrict__ x0, const float* __restrict__ x1)
{
    extern __shared__ uint32_t smemu[];
    uint32_t* sA = smemu;
    uint32_t* sB = smemu + 2*2560;
    int s = blockIdx.z;
    int Lc   = phase ? L1 : L0;
    int Qlen = phase ? 512 : 65;
    const __half* hs = g_hseq + (size_t)s*HS_S;
    const uint32_t* Bw = g_twt2 + (size_t)(phase*2 + s)*768*48;
    int row0 = blockIdx.y*128;
    int tid = threadIdx.x;
    WARP_IDS
    float acc[2][4][4] = {};

    #define CONV_LOAD(buf, kcc) { \
        int ktap = (kcc) / 384; \
        int i0 = (kcc) - ktap*384; \
        _Pragma("unroll") for (int rep = 0; rep < 2; ++rep) { \
            int idx = tid + rep*256; \
            int rr = idx >> 2, seg = idx & 3; \
            int gr = row0 + rr; \
            int n = gr / Qlen, q = gr - n*Qlen; \
            int l = q - ktap; \
            bool val = (l >= 0 && l < Lc); \
            const __half* src = val ? &hs[((size_t)n*Lc + l)*384 + i0 + seg*8] : hs; \
            cp16z(&AH(buf,rr,seg*4), src, val); } \
        { \
            int k = tid >> 4, seg = tid & 15; \
            bool val = (seg*4 < 48); \
            const uint32_t* src = val ? &Bw[(size_t)(((kcc)>>1) + k)*48 + seg*4] : Bw; \
            cp16z(&BH64(buf,k,seg*4), src, val); } }

    CONV_LOAD(0, 0)
    cp_commit();
    for (int c = 0; c < 48; ++c) {
        int cur = c & 1;
        if (c < 47) {
            CONV_LOAD(cur^1, (c+1)*32)
            cp_commit();
            cp_wait1();
        } else cp_wait0();
        __syncthreads();
        MMA_H_N64(cur)
        __syncthreads();
    }
    #undef CONV_LOAD
    int g = phase*2 + s;
    #pragma unroll
    for (int mt = 0; mt < 2; ++mt) {
        int rbase = row0 + wm*32 + mt*16 + gp;
        #pragma unroll
        for (int nt = 0; nt < 4; ++nt) {
            int cb = wn*32 + nt*8 + 2*qn;
            #pragma unroll
            for (int half = 0; half < 2; ++half) {
                int row = rbase + half*8;
                int n = row / Qlen, q = row - n*Qlen;
                #pragma unroll
                for (int j = 0; j < 2; ++j) {
                    int c = cb + j;
                    if (c < 48) {
                        float v = acc[mt][nt][half*2 + j] + Tb[g*48 + c];
                        if (phase == 0) {
                            int b = n >> 9, tpos = n & 511;
                            size_t oi = ((size_t)(b*48 + c)*512 + tpos)*65 + q;
                            const float* res = s ? x1 : x0;
                            g_io[(size_t)s*TSZ + oi] = v + res[oi];
                        } else {
                            int b = n / 65, f = n - b*65;
                            size_t oi = ((size_t)(b*48 + c)*512 + q)*65 + f;
                            g_eo[(size_t)s*TSZ + oi] = v + g_io[(size_t)s*TSZ + oi];
                        }
                    }
                }
            }
        }
    }
}

// ---------------- q/k/v head projections + leaky + LN (K written transposed) ----------------
__global__ void __launch_bounds__(256) qkv_kernel(
    const float* __restrict__ AWqk, const float* __restrict__ Abqk, const float* __restrict__ Aaqk,
    const float* __restrict__ Agqk, const float* __restrict__ Abgqk,
    const float* __restrict__ AWv,  const float* __restrict__ Abv,  const float* __restrict__ Aav,
    const float* __restrict__ Agv,  const float* __restrict__ Abgv)
{
    int t = blockIdx.x, b = blockIdx.y, s = blockIdx.z, tid = threadIdx.x;
    int lane = tid & 31, warp = tid >> 5;
    __shared__ float zs[3120];
    __shared__ float buf[780];
    __shared__ float red[32];
    const float* z = g_eo + (size_t)s*TSZ;
    for (int i = tid; i < 3120; i += 256) {
        int c = i / 65, f = i - c*65;
        zs[i] = z[((size_t)(b*48 + c)*512 + t)*65 + f];
    }
    __syncthreads();
    for (int grp = 0; grp < 12; ++grp) {
        int tensor = grp >> 2, h = grp & 3;
        int nvals;
        const float *W, *bb, *gam, *bet;
        float alpha;
        if (tensor < 2) {
            nvals = 520;
            int hh = (s*2 + tensor)*4 + h;
            W = AWqk + (size_t)hh*8*48; bb = Abqk + hh*8; alpha = Aaqk[hh];
            gam = Agqk + (size_t)hh*8*65; bet = Abgqk + (size_t)hh*8*65;
        } else {
            nvals = 780;
            int hh = s*4 + h;
            W = AWv + (size_t)hh*12*48; bb = Abv + hh*12; alpha = Aav[hh];
            gam = Agv + (size_t)hh*12*65; bet = Abgv + (size_t)hh*12*65;
        }
        float ls = 0.f, lq = 0.f;
        for (int idx = tid; idx < nvals; idx += 256) {
            int e = idx / 65, f = idx - e*65;
            float a = bb[e];
            const float* wr = W + e*48;
            #pragma unroll
            for (int c = 0; c < 48; ++c) a += zs[c*65 + f]*wr[c];
            a = a >= 0.f ? a : alpha*a;
            buf[idx] = a; ls += a; lq += a*a;
        }
        #pragma unroll
        for (int o = 16; o; o >>= 1) {
            ls += __shfl_xor_sync(0xffffffffu, ls, o);
            lq += __shfl_xor_sync(0xffffffffu, lq, o);
        }
        if (lane == 0) { red[warp] = ls; red[8 + warp] = lq; }
        __syncthreads();
        if (tid == 0) {
            float a = 0.f, c = 0.f;
            #pragma unroll
            for (int i = 0; i < 8; ++i) { a += red[i]; c += red[8 + i]; }
            red[16] = a; red[17] = c;
        }
        __syncthreads();
        float mu = red[16] / nvals;
        float inv = rsqrtf(red[17] / nvals - mu*mu + EPSLN);
        int bz = s*16 + b*4 + h;
        if (tensor == 0) {
            float* outp = g_q + ((size_t)bz*512 + t)*EK2;
            for (int idx = tid; idx < nvals; idx += 256)
                outp[idx] = (buf[idx] - mu)*inv*gam[idx] + bet[idx];
            if (tid < EK2 - 520) outp[520 + tid] = 0.f;
        } else if (tensor == 1) {
            float* outp = g_k + (size_t)bz*EK2*512;
            for (int idx = tid; idx < nvals; idx += 256)
                outp[(size_t)idx*512 + t] = (buf[idx] - mu)*inv*gam[idx] + bet[idx];
            if (tid < EK2 - 520) outp[(size_t)(520 + tid)*512 + t] = 0.f;
        } else {
            float* outp = g_v + ((size_t)bz*512 + t)*780;
            for (int idx = tid; idx < nvals; idx += 256)
                outp[idx] = (buf[idx] - mu)*inv*gam[idx] + bet[idx];
        }
        __syncthreads();
    }
}

// ---------------- QK^T (scaled, tf32 XL) ----------------
__global__ void __launch_bounds__(256, 2) qk_gemm()
{
    extern __shared__ uint32_t smemu[];
    uint32_t* sA = smemu;
    uint32_t* sB = smemu + 2*4608;
    int bz = blockIdx.z;
    const float* Q  = g_q + (size_t)bz*512*EK2;
    const float* Kt = g_k + (size_t)bz*EK2*512;
    float* Co = g_attn + (size_t)bz*512*512;
    int row0 = blockIdx.y*128, col0 = blockIdx.x*128;
    int tid = threadIdx.x;
    WARP_IDS
    float acc[2][8][4] = {};
    LOAD_A128F(0, Q, EK2, 511, 0)
    LOAD_BXLF(0, Kt, 512, 0)
    cp_commit();
    for (int c = 0; c < 17; ++c) {
        int cur = c & 1;
        if (c < 16) {
            LOAD_A128F(cur^1, Q, EK2, 511, (c+1)*32)
            LOAD_BXLF(cur^1, Kt, 512, (c+1)*32)
            cp_commit();
            cp_wait1();
        } else cp_wait0();
        __syncthreads();
        MMA_XLF(cur)
        __syncthreads();
    }
    float rs = rsqrtf(520.f);
    #pragma unroll
    for (int mt = 0; mt < 2; ++mt) {
        int r = row0 + wm*32 + mt*16 + gp;
        #pragma unroll
        for (int nt = 0; nt < 8; ++nt) {
            int cb = col0 + wn*64 + nt*8 + 2*qn;
            *(float2*)&Co[(size_t)r*512 + cb]     = make_float2(acc[mt][nt][0]*rs, acc[mt][nt][1]*rs);
            *(float2*)&Co[(size_t)(r+8)*512 + cb] = make_float2(acc[mt][nt][2]*rs, acc[mt][nt][3]*rs);
        }
    }
}

// ---------------- row softmax ----------------
__global__ void __launch_bounds__(256) softmax_rows()
{
    int row = blockIdx.x, bz = blockIdx.y, tid = threadIdx.x;
    float* p = g_attn + (size_t)bz*512*512 + (size_t)row*512;
    __shared__ float sm[512];
    __shared__ float red[256];
    sm[tid] = p[tid]; sm[tid + 256] = p[tid + 256];
    red[tid] = fmaxf(sm[tid], sm[tid + 256]);
    __syncthreads();
    for (int st = 128; st > 0; st >>= 1) {
        if (tid < st) red[tid] = fmaxf(red[tid], red[tid + st]);
        __syncthreads();
    }
    float mx = red[0];
    __syncthreads();
    float e0 = expf(sm[tid] - mx), e1 = expf(sm[tid + 256] - mx);
    red[tid] = e0 + e1;
    __syncthreads();
    for (int st = 128; st > 0; st >>= 1) {
        if (tid < st) red[tid] += red[tid + st];
        __syncthreads();
    }
    float invs = 1.f / red[0];
    p[tid] = e0*invs; p[tid + 256] = e1*invs;
}

// ---------------- P @ V (tf32 XL) ----------------
__global__ void __launch_bounds__(256, 2) pv_gemm()
{
    extern __shared__ uint32_t smemu[];
    uint32_t* sA = smemu;
    uint32_t* sB = smemu + 2*4608;
    int bz = blockIdx.z;
    const float* A  = g_attn + (size_t)bz*512*512;
    const float* Bv = g_v + (size_t)bz*512*780;
    float* Co = g_av + (size_t)bz*512*780;
    int row0 = blockIdx.y*128, col0 = blockIdx.x*128;
    int tid = threadIdx.x;
    WARP_IDS
    float acc[2][8][4] = {};
    LOAD_A128F(0, A, 512, 511, 0)
    LOAD_BXLF_G(0, Bv, 780, 0, 780)
    cp_commit();
    for (int c = 0; c < 16; ++c) {
        int cur = c & 1;
        if (c < 15) {
            LOAD_A128F(cur^1, A, 512, 511, (c+1)*32)
            LOAD_BXLF_G(cur^1, Bv, 780, (c+1)*32, 780)
            cp_commit();
            cp_wait1();
        } else cp_wait0();
        __syncthreads();
        MMA_XLF(cur)
        __syncthreads();
    }
    #pragma unroll
    for (int mt = 0; mt < 2; ++mt) {
        int r = row0 + wm*32 + mt*16 + gp;
        #pragma unroll
        for (int nt = 0; nt < 8; ++nt) {
            int cb = col0 + wn*64 + nt*8 + 2*qn;
            #pragma unroll
            for (int j = 0; j < 2; ++j) {
                int col = cb + j;
                if (col < 780) {
                    Co[(size_t)r*780 + col]     = acc[mt][nt][j];
                    Co[(size_t)(r+8)*780 + col] = acc[mt][nt][2 + j];
                }
            }
        }
    }
}

// ---------------- output projection + leaky + LN + residual ----------------
__global__ void __launch_bounds__(256) outproj_kernel(
    const float* __restrict__ AWp, const float* __restrict__ Abp, const float* __restrict__ Aap,
    const float* __restrict__ Agp, const float* __restrict__ Abgp, float* __restrict__ dout)
{
    int t = blockIdx.x, b = blockIdx.y, s = blockIdx.z, tid = threadIdx.x;
    int lane = tid & 31, warp = tid >> 5;
    __shared__ float os[3120];
    __shared__ float buf[3120];
    __shared__ float red[32];
    for (int i = tid; i < 3120; i += 256) {
        int c = i / 65, f = i - c*65;
        int h = c / 12, dv = c - h*12;
        os[i] = g_av[((size_t)((s*16 + b*4 + h)*512) + t)*780 + dv*65 + f];
    }
    __syncthreads();
    float alpha = Aap[s];
    float ls = 0.f, lq = 0.f;
    for (int idx = tid; idx < 3120; idx += 256) {
        int o = idx / 65, f = idx - o*65;
        float a = Abp[s*48 + o];
        const float* wr = AWp + (size_t)(s*48 + o)*48;
        #pragma unroll
        for (int c = 0; c < 48; ++c) a += os[c*65 + f]*wr[c];
        a = a >= 0.f ? a : alpha*a;
        buf[idx] = a; ls += a; lq += a*a;
    }
    #pragma unroll
    for (int o = 16; o; o >>= 1) {
        ls += __shfl_xor_sync(0xffffffffu, ls, o);
        lq += __shfl_xor_sync(0xffffffffu, lq, o);
    }
    if (lane == 0) { red[warp] = ls; red[8 + warp] = lq; }
    __syncthreads();
    if (tid == 0) {
        float a = 0.f, c = 0.f;
        #pragma unroll
        for (int i = 0; i < 8; ++i) { a += red[i]; c += red[8 + i]; }
        red[16] = a; red[17] = c;
    }
    __syncthreads();
    float mu = red[16] / 3120.f;
    float inv = rsqrtf(red[17] / 3120.f - mu*mu + EPSLN);
    for (int idx = tid; idx < 3120; idx += 256) {
        int o = idx / 65, f = idx - o*65;
        float v = (buf[idx] - mu)*inv*Agp[(s*48 + o)*65 + f] + Abgp[(s*48 + o)*65 + f]
                + g_eo[(size_t)s*TSZ + ((size_t)(b*48 + o)*512 + t)*65 + f];
        dout[(((size_t)(s*4 + b)*48 + o)*512 + t)*65 + f] = v;
    }
}

// ---------------- host launch ----------------
extern "C" void kernel_launch(void* const* d_in, const int* in_sizes, int n_in,
                              void* d_out, int out_size)
{
    const float* x     = (const float*)d_in[0];
    const float* c2    = (const float*)d_in[1];
    const float* ng    = (const float*)d_in[2];
    const float* nb    = (const float*)d_in[3];
    const float* LWih  = (const float*)d_in[4];
    const float* LWhh  = (const float*)d_in[5];
    const float* Lb    = (const float*)d_in[6];
    const float* TW    = (const float*)d_in[7];
    const float* Tb    = (const float*)d_in[8];
    const float* AWqk  = (const float*)d_in[9];
    const float* Abqk  = (const float*)d_in[10];
    const float* Aaqk  = (const float*)d_in[11];
    const float* Agqk  = (const float*)d_in[12];
    const float* Abgqk = (const float*)d_in[13];
    const float* AWv   = (const float*)d_in[14];
    const float* Abv   = (const float*)d_in[15];
    const float* Aav   = (const float*)d_in[16];
    const float* Agv   = (const float*)d_in[17];
    const float* Abgv  = (const float*)d_in[18];
    const float* AWp   = (const float*)d_in[19];
    const float* Abp   = (const float*)d_in[20];
    const float* Aap   = (const float*)d_in[21];
    const float* Agp   = (const float*)d_in[22];
    const float* Abgp  = (const float*)d_in[23];
    float* out = (float*)d_out;

    cudaFuncSetAttribute(xw_gemm,    cudaFuncAttributeMaxDynamicSharedMemorySize, SMEM_H128);
    cudaFuncSetAttribute(lstm_seq,   cudaFuncAttributeMaxDynamicSharedMemorySize, SMEM_SEQ);
    cudaFuncSetAttribute(convt_gemm, cudaFuncAttributeMaxDynamicSharedMemorySize, SMEM_H64);
    cudaFuncSetAttribute(qk_gemm,    cudaFuncAttributeMaxDynamicSharedMemorySize, SMEM_XL);
    cudaFuncSetAttribute(pv_gemm,    cudaFuncAttributeMaxDynamicSharedMemorySize, SMEM_XL);

    pack_weights<<<512, 256>>>(LWih, LWhh, Lb, TW);

    // ---- phase 0: intra ----
    ln_unfold_intra<<<dim3(512, 4, 2), 256>>>(x, c2, ng, nb);
    xw_gemm<<<dim3(6, (ROWS0 + 127)/128, 4), 256, SMEM_H128>>>(0, ROWS0);
    lstm_seq<<<dim3(N0/16, 4), 256, SMEM_SEQ>>>(0, N0, L0);
    convt_gemm<<<dim3(1, CONV_ROWS/128, 2), 256, SMEM_H64>>>(0, Tb, x, c2);

    // ---- phase 1: inter ----
    ln_unfold_inter<<<dim3(512, 4, 2), 256>>>(ng, nb);
    xw_gemm<<<dim3(6, (ROWS1 + 127)/128, 4), 256, SMEM_H128>>>(1, ROWS1);
    lstm_seq<<<dim3((N1 + 15)/16, 4), 256, SMEM_SEQ>>>(1, N1, L1);
    convt_gemm<<<dim3(1, CONV_ROWS/128, 2), 256, SMEM_H64>>>(1, Tb, x, c2);

    // ---- attention ----
    qkv_kernel<<<dim3(512, 4, 2), 256>>>(AWqk, Abqk, Aaqk, Agqk, Abgqk,
                                         AWv, Abv, Aav, Agv, Abgv);
    qk_gemm<<<dim3(4, 4, 32), 256, SMEM_XL>>>();
    softmax_rows<<<dim3(512, 32), 256>>>();
    pv_gemm<<<dim3(7, 4, 32), 256, SMEM_XL>>>();
    outproj_kernel<<<dim3(512, 4, 2), 256>>>(AWp, Abp, Aap, Agp, Abgp, out);
}